// round 13
// baseline (speedup 1.0000x reference)
#include <cuda_runtime.h>
#include <cuda_fp16.h>

#define N_NODES 50000
#define N_EDGES 300000
#define SQRT3_INV 0.57735026918962576451f
#define ALPHA_C   0.20412414523193150818f   /* 1/sqrt(24) */
#define BN_EPS    1e-5f

typedef unsigned int u32;

/* ---------------- scratch (no allocation allowed) ---------------- */
__device__ float g_agg[N_NODES * 48];
__device__ float g_tmp[N_NODES * 40];
__device__ float g_stats[40];
__device__ __half g_w2t_h[64 * 64];      /* [n][k] transposed, fp16 */
__device__ __half g_w3t_h[768 * 64];     /* [w][k] transposed, fp16 */

__device__ __forceinline__ float silu_f(float x)    { return x / (1.f + __expf(-x)); }
__device__ __forceinline__ float sigmoid_f(float x) { return 1.f / (1.f + __expf(-x)); }

__device__ __forceinline__ u32 s2u(const void* p) {
    u32 a;
    asm("{ .reg .u64 t; cvta.to.shared.u64 t, %1; cvt.u32.u64 %0, t; }" : "=r"(a) : "l"(p));
    return a;
}
__device__ __forceinline__ void f16split(float x, u32& h, u32& l) {
    __half hb = __float2half(x);
    __half lb = __float2half(x - __half2float(hb));
    h = (u32)__half_as_ushort(hb);
    l = (u32)__half_as_ushort(lb);
}
/* packed u32 (2 halves) -> float2 */
__device__ __forceinline__ float2 h2f2(u32 v) {
    __half2 h = *reinterpret_cast<__half2*>(&v);
    return __half22float2(h);
}

#define LDSM4(R, ADDR) \
    asm volatile("ldmatrix.sync.aligned.m8n8.x4.shared.b16 {%0,%1,%2,%3}, [%4];" \
        : "=r"((R)[0]), "=r"((R)[1]), "=r"((R)[2]), "=r"((R)[3]) : "r"(ADDR))

#define MMA_F16(C, A, B0, B1) \
    asm volatile("mma.sync.aligned.m16n8k16.row.col.f32.f16.f16.f32 " \
        "{%0,%1,%2,%3}, {%4,%5,%6,%7}, {%8,%9}, {%0,%1,%2,%3};" \
        : "+f"((C)[0]), "+f"((C)[1]), "+f"((C)[2]), "+f"((C)[3]) \
        : "r"((A)[0]), "r"((A)[1]), "r"((A)[2]), "r"((A)[3]), "r"(B0), "r"(B1))

/* named barriers: FULL[p] = 1+p, EMPTY[p] = 3+p */
#define BARS(id) asm volatile("bar.sync %0, 256;"   :: "r"(id) : "memory")
#define BARA(id) asm volatile("bar.arrive %0, 256;" :: "r"(id) : "memory")

/* ---------------- smem layout (bytes); rows padded to 72 halves --- */
constexpr int SM_A_HI = 0;         /* 64 x 144B */
constexpr int SM_A_LO = 9216;
constexpr int SM_B0   = 18432;     /* 64 x 144B, fp16 */
constexpr int SM_B1   = 27648;
constexpr int SM_P0   = 36864;     /* 64 x 144B, fp16 (72-half rows) */
constexpr int SM_P1   = 46080;
constexpr int SM_W1   = 55296;     /* 512 f  */
constexpr int SM_B1b  = 57344;     /* 64 f   */
constexpr int SM_B2   = 57600;     /* 64 f   */
constexpr int SM_B3   = 57856;     /* 768 f  */
constexpr int SM_SH0  = 60928;     /* 64 f   */
constexpr int SM_SH1  = 61184;     /* 64x4 f */
constexpr int SM_BAS  = 62208;     /* 64x9 f */
constexpr int SM_SX   = 64512;     /* 64x17 f */
constexpr int SM_CB   = 68864;     /* 64x9 f */
constexpr int SM_VS   = 71168;     /* 64x25 f */
constexpr int SM_SRC  = 77568;     /* 64 int */
constexpr int SM_DST  = 77824;     /* 64 int */
constexpr int SM_SXA  = 78080;     /* 64x16 f (sx * sh0) */
constexpr int SM_TOTAL = 82176;

/* ============ prep: transpose W2, W3 to fp16 ====================== */
__global__ void prep_kernel(const float* __restrict__ W2, const float* __restrict__ W3)
{
    int i = blockIdx.x * 256 + threadIdx.x;
    if (i < 64 * 64) {
        int n = i >> 6, k = i & 63;
        g_w2t_h[i] = __float2half(W2[k * 64 + n]);
    }
    if (i < 768 * 64) {
        int w = i >> 6, k = i & 63;
        g_w3t_h[i] = __float2half(W3[k * 768 + w]);
    }
}

/* split 16 fp32 -> fp16 hi/lo pairs, store one A row segment         */
__device__ __forceinline__ void split_store16(char* sm, int e, int j0, const float* xv)
{
    u32 hi[8], lo[8];
#pragma unroll
    for (int p = 0; p < 8; p++) {
        u32 h0, l0, h1, l1;
        f16split(xv[2 * p], h0, l0);
        f16split(xv[2 * p + 1], h1, l1);
        hi[p] = h0 | (h1 << 16);
        lo[p] = l0 | (l1 << 16);
    }
    u32 off = (u32)e * 144 + (u32)j0 * 2;
    *(uint4*)(sm + SM_A_HI + off)      = make_uint4(hi[0], hi[1], hi[2], hi[3]);
    *(uint4*)(sm + SM_A_HI + off + 16) = make_uint4(hi[4], hi[5], hi[6], hi[7]);
    *(uint4*)(sm + SM_A_LO + off)      = make_uint4(lo[0], lo[1], lo[2], lo[3]);
    *(uint4*)(sm + SM_A_LO + off + 16) = make_uint4(lo[4], lo[5], lo[6], lo[7]);
}

/* hi-only variant (H2 single-term A path)                            */
__device__ __forceinline__ void store16_hi(char* sm, int e, int j0, const float* xv)
{
    u32 hi[8];
#pragma unroll
    for (int p = 0; p < 8; p++) {
        u32 h0 = (u32)__half_as_ushort(__float2half(xv[2 * p]));
        u32 h1 = (u32)__half_as_ushort(__float2half(xv[2 * p + 1]));
        hi[p] = h0 | (h1 << 16);
    }
    u32 off = (u32)e * 144 + (u32)j0 * 2;
    *(uint4*)(sm + SM_A_HI + off)      = make_uint4(hi[0], hi[1], hi[2], hi[3]);
    *(uint4*)(sm + SM_A_HI + off + 16) = make_uint4(hi[4], hi[5], hi[6], hi[7]);
}

/* =================== edge kernel (warp-specialized) =============== */
__global__ void __launch_bounds__(256, 2)
edge_kernel(const float* __restrict__ nf,  const float* __restrict__ esh,
            const float* __restrict__ ebas, const int*  __restrict__ eidx,
            const float* __restrict__ W1,  const float* __restrict__ b1,
            const float* __restrict__ b2p, const float* __restrict__ b3p)
{
    extern __shared__ char sm[];
    const u32 sbv = s2u(sm);
    const int tid = threadIdx.x;
    const int wid = tid >> 5, lane = tid & 31;
    const int e = tid >> 2, q = tid & 3;
    const int ge = blockIdx.x * 64 + e;
    const bool active = ge < N_EDGES;
    int* sSrc = (int*)(sm + SM_SRC);
    int* sDst = (int*)(sm + SM_DST);

    /* ---- prologue (all 256 threads) ---- */
    if (tid < 128) ((float4*)(sm + SM_W1))[tid] = ((const float4*)W1)[tid];
    if (tid < 16)               ((float4*)(sm + SM_B1b))[tid]     = ((const float4*)b1)[tid];
    else if (tid < 32)          ((float4*)(sm + SM_B2))[tid - 16] = ((const float4*)b2p)[tid - 16];
    if (tid >= 32 && tid < 224) ((float4*)(sm + SM_B3))[tid - 32] = ((const float4*)b3p)[tid - 32];
#pragma unroll
    for (int s = 0; s < 2; s++) {                      /* B0 <- W2T, B1 <- W3 chunk 0 */
        int v = tid + s * 256;
        u32 doff = (u32)(v >> 3) * 144 + (u32)(v & 7) * 16;
        *(uint4*)(sm + SM_B0 + doff) = ((const uint4*)g_w2t_h)[v];
        *(uint4*)(sm + SM_B1 + doff) = ((const uint4*)g_w3t_h)[v];
    }
    if (q == 0) {
        float4 sh = active ? *(const float4*)(esh + (size_t)ge * 4) : make_float4(0, 0, 0, 0);
        ((float*)(sm + SM_SH0))[e] = sh.x;
        ((float*)(sm + SM_SH1))[e * 4 + 0] = sh.y;
        ((float*)(sm + SM_SH1))[e * 4 + 1] = sh.z;
        ((float*)(sm + SM_SH1))[e * 4 + 2] = sh.w;
        sSrc[e] = active ? eidx[ge] : 0;
        sDst[e] = active ? eidx[N_EDGES + ge] : 0;
    } else if (q == 1) {
        float4 bA = active ? *(const float4*)(ebas + (size_t)ge * 8)     : make_float4(0, 0, 0, 0);
        float4 bB = active ? *(const float4*)(ebas + (size_t)ge * 8 + 4) : make_float4(0, 0, 0, 0);
        float* bs = (float*)(sm + SM_BAS) + e * 9;
        bs[0] = bA.x; bs[1] = bA.y; bs[2] = bA.z; bs[3] = bA.w;
        bs[4] = bB.x; bs[5] = bB.y; bs[6] = bB.z; bs[7] = bB.w;
    }
    __syncthreads();

    {   /* gather node features + coefficients */
        const int src = sSrc[e];
        const float* nfr = nf + (size_t)src * 40;
        const float sh0 = ((float*)(sm + SM_SH0))[e];
        const float s1x = ((float*)(sm + SM_SH1))[e * 4 + 0];
        const float s1y = ((float*)(sm + SM_SH1))[e * 4 + 1];
        const float s1z = ((float*)(sm + SM_SH1))[e * 4 + 2];
        for (int u = q; u < 16; u += 4) {
            float sx = active ? nfr[u] : 0.f;
            ((float*)(sm + SM_SX))[e * 17 + u]  = sx;
            ((float*)(sm + SM_SXA))[e * 16 + u] = sx * sh0;
        }
        for (int u = q; u < 8; u += 4) {
            float v0 = active ? nfr[16 + u * 3 + 0] : 0.f;
            float v1 = active ? nfr[16 + u * 3 + 1] : 0.f;
            float v2 = active ? nfr[16 + u * 3 + 2] : 0.f;
            float* vs = (float*)(sm + SM_VS);
            vs[e * 25 + u * 3 + 0] = v0 * sh0;
            vs[e * 25 + u * 3 + 1] = v1 * sh0;
            vs[e * 25 + u * 3 + 2] = v2 * sh0;
            ((float*)(sm + SM_CB))[e * 9 + u] = (v0 * s1x + v1 * s1y + v2 * s1z) * SQRT3_INV;
        }
    }

    {   /* H1 = silu(basis @ W1 + b1) -> A hi/lo (round 0 is 2-term) */
        const float* w1s = (const float*)(sm + SM_W1);
        const float* b1s = (const float*)(sm + SM_B1b);
        const float* bs  = (const float*)(sm + SM_BAS) + e * 9;
        float bk[8];
#pragma unroll
        for (int k = 0; k < 8; k++) bk[k] = bs[k];
        const int j0 = q * 16;
        float xv[16];
#pragma unroll
        for (int jj = 0; jj < 16; jj++) {
            float x = b1s[j0 + jj];
#pragma unroll
            for (int k = 0; k < 8; k++) x += bk[k] * w1s[k * 64 + j0 + jj];
            xv[jj] = silu_f(x);
        }
        split_store16(sm, e, j0, xv);
    }
    __syncthreads();

    if (wid < 4) {
        /* ========== PRODUCER: 2x2 warp tiling (M32 x N32 each) ===== */
        const int mi = wid & 1, ni = wid >> 1;
        const int m0 = mi * 32, n0 = ni * 32;
        const u32 arow = (u32)(m0 + ((lane >> 3) & 1) * 8 + (lane & 7)) * 144
                       + (u32)((lane >> 4) & 1) * 16;
        const u32 boffr = (u32)(((lane >> 4) & 1) * 8 + (lane & 7)) * 144
                        + (u32)((lane >> 3) & 1) * 16;
        const int cg = lane >> 2, c2 = (lane & 3) * 2;

        u32 ah[2][4][4];

        /* ---- round 0: P = H1 @ W2^T, 2-term; hi->P0, lo->P1 ---- */
        {
            u32 al[2][4][4];
#pragma unroll
            for (int mt = 0; mt < 2; mt++)
#pragma unroll
                for (int ks = 0; ks < 4; ks++) {
                    LDSM4(ah[mt][ks], sbv + SM_A_HI + arow + mt * 2304 + ks * 32);
                    LDSM4(al[mt][ks], sbv + SM_A_LO + arow + mt * 2304 + ks * 32);
                }
            float acc[2][4][4];
#pragma unroll
            for (int mt = 0; mt < 2; mt++)
#pragma unroll
                for (int nt = 0; nt < 4; nt++)
#pragma unroll
                    for (int i = 0; i < 4; i++) acc[mt][nt][i] = 0.f;
#pragma unroll
            for (int ks = 0; ks < 4; ks++) {
                u32 bh[8];
                LDSM4(&bh[0], sbv + SM_B0 + boffr + (u32)n0 * 144 + ks * 32);
                LDSM4(&bh[4], sbv + SM_B0 + boffr + (u32)(n0 + 16) * 144 + ks * 32);
#pragma unroll
                for (int mt = 0; mt < 2; mt++)
#pragma unroll
                    for (int nt = 0; nt < 4; nt++) {
                        MMA_F16(acc[mt][nt], ah[mt][ks], bh[nt * 2], bh[nt * 2 + 1]);
                        MMA_F16(acc[mt][nt], al[mt][ks], bh[nt * 2], bh[nt * 2 + 1]);
                    }
            }
            const float* bias = (const float*)(sm + SM_B2);
#pragma unroll
            for (int nt = 0; nt < 4; nt++) {
                const int col = n0 + nt * 8 + c2;
                float2 bv = *(const float2*)&bias[col];
#pragma unroll
                for (int mt = 0; mt < 2; mt++) {
                    const int row0 = m0 + mt * 16 + cg;
                    float v0 = acc[mt][nt][0] + bv.x, v1 = acc[mt][nt][1] + bv.y;
                    float v2 = acc[mt][nt][2] + bv.x, v3 = acc[mt][nt][3] + bv.y;
                    __half2 h01 = __floats2half2_rn(v0, v1);
                    __half2 h23 = __floats2half2_rn(v2, v3);
                    *(__half2*)(sm + SM_P0 + row0 * 144 + col * 2)       = h01;
                    *(__half2*)(sm + SM_P0 + (row0 + 8) * 144 + col * 2) = h23;
                    __half2 l01 = __floats2half2_rn(v0 - __low2float(h01), v1 - __high2float(h01));
                    __half2 l23 = __floats2half2_rn(v2 - __low2float(h23), v3 - __high2float(h23));
                    *(__half2*)(sm + SM_P1 + row0 * 144 + col * 2)       = l01;
                    *(__half2*)(sm + SM_P1 + (row0 + 8) * 144 + col * 2) = l23;
                }
            }
            BARA(1);                                 /* FULL0 */
            BARS(3);                                 /* EMPTY0: H2 in A smem */
#pragma unroll
            for (int mt = 0; mt < 2; mt++)
#pragma unroll
                for (int ks = 0; ks < 4; ks++)
                    LDSM4(ah[mt][ks], sbv + SM_A_HI + arow + mt * 2304 + ks * 32);
        }

        /* ---- rounds 1..12: single-term A (hi only) ---- */
#pragma unroll 1
        for (int r = 1; r <= 12; r++) {
            const int p = r & 1;
            if (r >= 3) BARS(3 + p);                 /* EMPTY[p] */
            const u32 baseB = sbv + (p ? SM_B1 : SM_B0);
            float acc[2][4][4];
#pragma unroll
            for (int mt = 0; mt < 2; mt++)
#pragma unroll
                for (int nt = 0; nt < 4; nt++)
#pragma unroll
                    for (int i = 0; i < 4; i++) acc[mt][nt][i] = 0.f;
#pragma unroll
            for (int ks = 0; ks < 4; ks++) {
                u32 bh[8];
                LDSM4(&bh[0], baseB + boffr + (u32)n0 * 144 + ks * 32);
                LDSM4(&bh[4], baseB + boffr + (u32)(n0 + 16) * 144 + ks * 32);
#pragma unroll
                for (int mt = 0; mt < 2; mt++)
#pragma unroll
                    for (int nt = 0; nt < 4; nt++)
                        MMA_F16(acc[mt][nt], ah[mt][ks], bh[nt * 2], bh[nt * 2 + 1]);
            }
            char* PB = sm + (p ? SM_P1 : SM_P0);
            const float* bias = (const float*)(sm + SM_B3) + (r - 1) * 64;
#pragma unroll
            for (int nt = 0; nt < 4; nt++) {
                const int col = n0 + nt * 8 + c2;
                float2 bv = *(const float2*)&bias[col];
#pragma unroll
                for (int mt = 0; mt < 2; mt++) {
                    const int row0 = m0 + mt * 16 + cg;
                    __half2 h01 = __floats2half2_rn(acc[mt][nt][0] + bv.x, acc[mt][nt][1] + bv.y);
                    __half2 h23 = __floats2half2_rn(acc[mt][nt][2] + bv.x, acc[mt][nt][3] + bv.y);
                    *(__half2*)(PB + row0 * 144 + col * 2)       = h01;
                    *(__half2*)(PB + (row0 + 8) * 144 + col * 2) = h23;
                }
            }
            BARA(1 + p);                             /* FULL[p] */
        }
    } else {
        /* =============== CONSUMER: warps 4-7 ======================= */
        const int tp = tid - 128;
        const int ce = tp >> 1, cq = tp & 1;
        const bool cact = (blockIdx.x * 64 + ce) < N_EDGES;
        const int eP = ce * 144;                     /* byte row offset in P */
        const float* sxs = (const float*)(sm + SM_SX) + ce * 17;
        const float* sxa = (const float*)(sm + SM_SXA) + ce * 16;
        const float* cbs = (const float*)(sm + SM_CB) + ce * 9;
        const float* vse = (const float*)(sm + SM_VS) + ce * 25;

        /* pair accumulators: s pairs p=2t+cq (t=0..5), v pairs p=2t+cq (t=0..1) */
        float2 rs2[6], rtsv2[2], rv2[2][3];
#pragma unroll
        for (int k = 0; k < 6; k++) rs2[k] = make_float2(0.f, 0.f);
#pragma unroll
        for (int t = 0; t < 2; t++) {
            rtsv2[t] = make_float2(0.f, 0.f);
            rv2[t][0] = make_float2(0.f, 0.f);
            rv2[t][1] = make_float2(0.f, 0.f);
            rv2[t][2] = make_float2(0.f, 0.f);
        }

#pragma unroll
        for (int r = 0; r <= 12; r++) {
            BARS(1 + (r & 1));                       /* FULL[p] */
            if (r <= 10) {                           /* stage W3 chunk r+1 */
                char* dB = sm + ((r & 1) ? SM_B1 : SM_B0);
                const uint4* srcB = ((const uint4*)g_w3t_h) + (r + 1) * 512;
#pragma unroll
                for (int s = 0; s < 4; s++) {
                    int v = tp + s * 128;
                    u32 doff = (u32)(v >> 3) * 144 + (u32)(v & 7) * 16;
                    *(uint4*)(dB + doff) = srcB[v];
                }
            }
            if (r == 0) {
                /* H2 = silu(hi+lo) -> A hi only (single-term W3 rounds) */
                const int j0 = cq * 32;
                float xv[16];
#pragma unroll
                for (int half = 0; half < 2; half++) {
#pragma unroll
                    for (int jj = 0; jj < 16; jj += 2) {
                        const int c = j0 + half * 16 + jj;
                        float2 hf = __half22float2(*(const __half2*)(sm + SM_P0 + eP + c * 2));
                        float2 lf = __half22float2(*(const __half2*)(sm + SM_P1 + eP + c * 2));
                        xv[jj]     = silu_f(hf.x + lf.x);
                        xv[jj + 1] = silu_f(hf.y + lf.y);
                    }
                    store16_hi(sm, ce, j0 + half * 16, xv);
                }
            } else {
                const char* PB = sm + ((r & 1) ? SM_P1 : SM_P0);
                /* vector-load whole P row into regs */
                u32 row[32];
#pragma unroll
                for (int i = 0; i < 8; i++) {
                    uint4 v4 = *(const uint4*)(PB + eP + i * 16);
                    row[i * 4 + 0] = v4.x; row[i * 4 + 1] = v4.y;
                    row[i * 4 + 2] = v4.z; row[i * 4 + 3] = v4.w;
                }
                const int cc = r - 1;
                if (cc < 9) {                        /* SS (cc<6) or VV */
                    const bool isSS = (cc < 6);
                    const int base = cc * 64;
                    const int sub = isSS ? 0 : 384;
                    const int bm2 = (base % 24) / 2;
                    const int d = (base - sub) / 24;
                    const float* coef = isSS ? sxa : cbs;
#pragma unroll
                    for (int t = 0; t < 6; t++) {
                        const int p = 2 * t + cq;            /* pair index 0..11 */
                        const int m = (p - bm2 + 12) % 12;   /* compile-time */
                        const int u0 = d + ((p < bm2) ? 1 : 0);
                        float2 a = make_float2(0.f, 0.f);
                        float2 x0 = h2f2(row[m]);
                        a.x += x0.x * coef[u0];      a.y += x0.y * coef[u0];
                        float2 x1 = h2f2(row[m + 12]);
                        a.x += x1.x * coef[u0 + 1];  a.y += x1.y * coef[u0 + 1];
                        if (m < 8) {
                            float2 x2 = h2f2(row[m + 24]);
                            a.x += x2.x * coef[u0 + 2];  a.y += x2.y * coef[u0 + 2];
                        }
                        rs2[t].x += a.x;  rs2[t].y += a.y;
                    }
                } else if (cc < 11) {                /* SV */
                    const int uoff = (cc == 9) ? 0 : 8;
#pragma unroll
                    for (int t = 0; t < 2; t++) {
                        const int p = 2 * t + cq;            /* v-pair 0..3 */
                        float2 a = make_float2(0.f, 0.f);
#pragma unroll
                        for (int u = 0; u < 8; u++) {
                            float2 x = h2f2(row[4 * u + p]);
                            a.x += x.x * sxs[uoff + u];
                            a.y += x.y * sxs[uoff + u];
                        }
                        rtsv2[t].x += a.x;  rtsv2[t].y += a.y;
                    }
                } else {                             /* VS */
#pragma unroll
                    for (int t = 0; t < 2; t++) {
                        const int p = 2 * t + cq;
                        float2 pv[8];
#pragma unroll
                        for (int u = 0; u < 8; u++)
                            pv[u] = h2f2(row[4 * u + p]);
#pragma unroll
                        for (int i = 0; i < 3; i++) {
                            float2 a = make_float2(0.f, 0.f);
#pragma unroll
                            for (int u = 0; u < 8; u++) {
                                a.x += pv[u].x * vse[u * 3 + i];
                                a.y += pv[u].y * vse[u * 3 + i];
                            }
                            rv2[t][i].x += a.x;  rv2[t][i].y += a.y;
                        }
                    }
                }
            }
            if (r <= 10) BARA(3 + (r & 1));          /* EMPTY[p] */
        }

        /* ---- finalize + scatter ---- */
        if (cact) {
            const int dst = sDst[ce];
            const float* sh1 = (const float*)(sm + SM_SH1) + ce * 4;
            float* ap = &g_agg[(size_t)dst * 48];
#pragma unroll
            for (int t = 0; t < 6; t++) {
                const int w = 2 * (2 * t + cq);              /* even output of pair */
                atomicAdd(ap + w,     rs2[t].x * ALPHA_C);
                atomicAdd(ap + w + 1, rs2[t].y * ALPHA_C);
            }
#pragma unroll
            for (int t = 0; t < 2; t++) {
                const int w = 2 * (2 * t + cq);              /* v pair: w, w+1 */
#pragma unroll
                for (int i = 0; i < 3; i++) {
                    atomicAdd(ap + 24 + w * 3 + i,
                              (rv2[t][i].x + rtsv2[t].x * sh1[i]) * ALPHA_C);
                    atomicAdd(ap + 24 + (w + 1) * 3 + i,
                              (rv2[t][i].y + rtsv2[t].y * sh1[i]) * ALPHA_C);
                }
            }
        }
    }
}

/* =================== node post-processing ========================= */
__global__ void zero_agg_kernel()
{
    int i = blockIdx.x * blockDim.x + threadIdx.x;
    if (i < N_NODES * 48) g_agg[i] = 0.f;
}
__global__ void zero_stats_kernel()
{
    if (threadIdx.x < 40) g_stats[threadIdx.x] = 0.f;
}

__global__ void node_kernel(const float* __restrict__ si_w0, const float* __restrict__ si_w1)
{
    __shared__ float w0[256], w1[64];
    int tid = threadIdx.x;
    if (tid < 256) w0[tid] = si_w0[tid] * 0.25f;
    if (tid < 64)  w1[tid] = si_w1[tid] * 0.35355339059327373f;
    __syncthreads();
    int n = blockIdx.x * blockDim.x + tid;
    if (n >= N_NODES) return;
    const float* a = &g_agg[(size_t)n * 48];
    float s[16], v[24];
#pragma unroll
    for (int u = 0; u < 16; u++) s[u] = silu_f(a[u]);
#pragma unroll
    for (int u = 0; u < 8; u++) {
        float g = sigmoid_f(a[16 + u]);
        v[u * 3 + 0] = a[24 + u * 3 + 0] * g;
        v[u * 3 + 1] = a[24 + u * 3 + 1] * g;
        v[u * 3 + 2] = a[24 + u * 3 + 2] * g;
    }
    float out[40];
#pragma unroll
    for (int w = 0; w < 16; w++) {
        float acc = 0.f;
#pragma unroll
        for (int u = 0; u < 16; u++) acc += s[u] * w0[u * 16 + w];
        out[w] = acc;
    }
#pragma unroll
    for (int w = 0; w < 8; w++) {
#pragma unroll
        for (int i = 0; i < 3; i++) {
            float acc = 0.f;
#pragma unroll
            for (int u = 0; u < 8; u++) acc += v[u * 3 + i] * w1[u * 8 + w];
            out[16 + w * 3 + i] = acc;
        }
    }
#pragma unroll
    for (int i = 0; i < 40; i += 4)
        *(float4*)&g_tmp[(size_t)n * 40 + i] = make_float4(out[i], out[i + 1], out[i + 2], out[i + 3]);
}

__global__ void stats_kernel()
{
    __shared__ float red[8 * 40];
    float acc[40];
#pragma unroll
    for (int i = 0; i < 40; i++) acc[i] = 0.f;
    for (int n = blockIdx.x * blockDim.x + threadIdx.x; n < N_NODES;
         n += gridDim.x * blockDim.x) {
        const float* t = &g_tmp[(size_t)n * 40];
#pragma unroll
        for (int c = 0; c < 16; c++) { float x = t[c]; acc[c] += x; acc[16 + c] += x * x; }
#pragma unroll
        for (int w = 0; w < 8; w++) {
            float x0 = t[16 + w * 3], x1 = t[17 + w * 3], x2 = t[18 + w * 3];
            acc[32 + w] += x0 * x0 + x1 * x1 + x2 * x2;
        }
    }
#pragma unroll
    for (int i = 0; i < 40; i++)
        for (int o = 16; o > 0; o >>= 1)
            acc[i] += __shfl_down_sync(0xffffffff, acc[i], o);
    int warp = threadIdx.x >> 5, lane = threadIdx.x & 31;
    if (lane == 0)
        for (int i = 0; i < 40; i++) red[warp * 40 + i] = acc[i];
    __syncthreads();
    if (threadIdx.x < 40) {
        float t = 0.f;
#pragma unroll
        for (int w = 0; w < 8; w++) t += red[w * 40 + threadIdx.x];
        atomicAdd(&g_stats[threadIdx.x], t);
    }
}

__global__ void finalize_kernel(const float* __restrict__ nf,
                                const float* __restrict__ bn_ws,
                                const float* __restrict__ bn_bs,
                                const float* __restrict__ bn_wv,
                                float* __restrict__ out)
{
    int t = blockIdx.x * blockDim.x + threadIdx.x;
    if (t >= N_NODES * 40) return;
    int c = t % 40;
    float val = g_tmp[t];
    const float invN = 1.f / (float)N_NODES;
    if (c < 16) {
        float m   = g_stats[c] * invN;
        float var = g_stats[16 + c] * invN - m * m;
        val = (val - m) * rsqrtf(var + BN_EPS) * bn_ws[c] + bn_bs[c];
    } else {
        int w = (c - 16) / 3;
        float vn = g_stats[32 + w] * (invN * (1.f / 3.f));
        val = val * rsqrtf(vn + BN_EPS) * bn_wv[w];
    }
    out[t] = val + nf[t];
}

/* ============================ launch ============================== */
extern "C" void kernel_launch(void* const* d_in, const int* in_sizes, int n_in,
                              void* d_out, int out_size)
{
    const float* nf    = (const float*)d_in[0];
    const float* esh   = (const float*)d_in[1];
    const float* ebas  = (const float*)d_in[2];
    const int*   eidx  = (const int*)  d_in[3];
    const float* W1    = (const float*)d_in[4];
    const float* b1    = (const float*)d_in[5];
    const float* W2    = (const float*)d_in[6];
    const float* b2    = (const float*)d_in[7];
    const float* W3    = (const float*)d_in[8];
    const float* b3    = (const float*)d_in[9];
    const float* si_w0 = (const float*)d_in[10];
    const float* si_w1 = (const float*)d_in[11];
    const float* bn_ws = (const float*)d_in[12];
    const float* bn_bs = (const float*)d_in[13];
    const float* bn_wv = (const float*)d_in[14];
    float* out = (float*)d_out;

    cudaFuncSetAttribute(edge_kernel, cudaFuncAttributeMaxDynamicSharedMemorySize, SM_TOTAL);

    /* launch order keeps edge_kernel at 0-indexed launch 3 (ncu slot) */
    prep_kernel<<<192, 256>>>(W2, W3);
    zero_agg_kernel<<<(N_NODES * 48 + 255) / 256, 256>>>();
    zero_stats_kernel<<<1, 64>>>();
    edge_kernel<<<(N_EDGES + 63) / 64, 256, SM_TOTAL>>>(nf, esh, ebas, eidx, W1, b1, b2, b3);
    node_kernel<<<(N_NODES + 255) / 256, 256>>>(si_w0, si_w1);
    stats_kernel<<<120, 256>>>();
    finalize_kernel<<<(N_NODES * 40 + 255) / 256, 256>>>(nf, bn_ws, bn_bs, bn_wv, out);
}

// round 14
// speedup vs baseline: 1.2878x; 1.2878x over previous
#include <cuda_runtime.h>
#include <cuda_fp16.h>

#define N_NODES 50000
#define N_EDGES 300000
#define SQRT3_INV 0.57735026918962576451f
#define ALPHA_C   0.20412414523193150818f   /* 1/sqrt(24) */
#define BN_EPS    1e-5f

typedef unsigned int u32;

/* ---------------- scratch (no allocation allowed) ---------------- */
__device__ float g_agg[N_NODES * 48];
__device__ float g_tmp[N_NODES * 40];
__device__ float g_stats[40];
__device__ __half g_w2t_h[64 * 64];      /* [n][k] transposed, fp16 */
__device__ __half g_w3t_h[768 * 64];     /* [w][k] transposed, fp16 */

__device__ __forceinline__ float silu_f(float x)    { return x / (1.f + __expf(-x)); }
__device__ __forceinline__ float sigmoid_f(float x) { return 1.f / (1.f + __expf(-x)); }

__device__ __forceinline__ u32 s2u(const void* p) {
    u32 a;
    asm("{ .reg .u64 t; cvta.to.shared.u64 t, %1; cvt.u32.u64 %0, t; }" : "=r"(a) : "l"(p));
    return a;
}
__device__ __forceinline__ void f16split(float x, u32& h, u32& l) {
    __half hb = __float2half(x);
    __half lb = __float2half(x - __half2float(hb));
    h = (u32)__half_as_ushort(hb);
    l = (u32)__half_as_ushort(lb);
}
/* extract fp16 (low/high per sh=0/16) from packed u32, to fp32 */
__device__ __forceinline__ float hsel(u32 v, u32 sh) {
    return __half2float(__ushort_as_half((unsigned short)(v >> sh)));
}

#define LDSM4(R, ADDR) \
    asm volatile("ldmatrix.sync.aligned.m8n8.x4.shared.b16 {%0,%1,%2,%3}, [%4];" \
        : "=r"((R)[0]), "=r"((R)[1]), "=r"((R)[2]), "=r"((R)[3]) : "r"(ADDR))

#define MMA_F16(C, A, B0, B1) \
    asm volatile("mma.sync.aligned.m16n8k16.row.col.f32.f16.f16.f32 " \
        "{%0,%1,%2,%3}, {%4,%5,%6,%7}, {%8,%9}, {%0,%1,%2,%3};" \
        : "+f"((C)[0]), "+f"((C)[1]), "+f"((C)[2]), "+f"((C)[3]) \
        : "r"((A)[0]), "r"((A)[1]), "r"((A)[2]), "r"((A)[3]), "r"(B0), "r"(B1))

/* named barriers: FULL[p] = 1+p, EMPTY[p] = 3+p */
#define BARS(id) asm volatile("bar.sync %0, 256;"   :: "r"(id) : "memory")
#define BARA(id) asm volatile("bar.arrive %0, 256;" :: "r"(id) : "memory")

/* ---------------- smem layout (bytes); rows padded to 72 halves --- */
constexpr int SM_A_HI = 0;         /* 64 x 144B */
constexpr int SM_A_LO = 9216;
constexpr int SM_B0   = 18432;     /* 64 x 144B, fp16 */
constexpr int SM_B1   = 27648;
constexpr int SM_P0   = 36864;     /* 64 x 144B, fp16 (72-half rows) */
constexpr int SM_P1   = 46080;
constexpr int SM_W1   = 55296;     /* 512 f  */
constexpr int SM_B1b  = 57344;     /* 64 f   */
constexpr int SM_B2   = 57600;     /* 64 f   */
constexpr int SM_B3   = 57856;     /* 768 f  */
constexpr int SM_SH0  = 60928;     /* 64 f   */
constexpr int SM_SH1  = 61184;     /* 64x4 f */
constexpr int SM_BAS  = 62208;     /* 64x9 f */
constexpr int SM_SX   = 64512;     /* 64x17 f */
constexpr int SM_CB   = 68864;     /* 64x9 f */
constexpr int SM_VS   = 71168;     /* 64x25 f */
constexpr int SM_SRC  = 77568;     /* 64 int */
constexpr int SM_DST  = 77824;     /* 64 int */
constexpr int SM_TOTAL = 78080;

/* ============ prep: transpose W2, W3 to fp16 ====================== */
__global__ void prep_kernel(const float* __restrict__ W2, const float* __restrict__ W3)
{
    int i = blockIdx.x * 256 + threadIdx.x;
    if (i < 64 * 64) {
        int n = i >> 6, k = i & 63;
        g_w2t_h[i] = __float2half(W2[k * 64 + n]);
    }
    if (i < 768 * 64) {
        int w = i >> 6, k = i & 63;
        g_w3t_h[i] = __float2half(W3[k * 768 + w]);
    }
}

/* split 16 fp32 -> fp16 hi/lo pairs, store one A row segment         */
__device__ __forceinline__ void split_store16(char* sm, int e, int j0, const float* xv)
{
    u32 hi[8], lo[8];
#pragma unroll
    for (int p = 0; p < 8; p++) {
        u32 h0, l0, h1, l1;
        f16split(xv[2 * p], h0, l0);
        f16split(xv[2 * p + 1], h1, l1);
        hi[p] = h0 | (h1 << 16);
        lo[p] = l0 | (l1 << 16);
    }
    u32 off = (u32)e * 144 + (u32)j0 * 2;
    *(uint4*)(sm + SM_A_HI + off)      = make_uint4(hi[0], hi[1], hi[2], hi[3]);
    *(uint4*)(sm + SM_A_HI + off + 16) = make_uint4(hi[4], hi[5], hi[6], hi[7]);
    *(uint4*)(sm + SM_A_LO + off)      = make_uint4(lo[0], lo[1], lo[2], lo[3]);
    *(uint4*)(sm + SM_A_LO + off + 16) = make_uint4(lo[4], lo[5], lo[6], lo[7]);
}

/* hi-only variant (H2 single-term A path)                            */
__device__ __forceinline__ void store16_hi(char* sm, int e, int j0, const float* xv)
{
    u32 hi[8];
#pragma unroll
    for (int p = 0; p < 8; p++) {
        u32 h0 = (u32)__half_as_ushort(__float2half(xv[2 * p]));
        u32 h1 = (u32)__half_as_ushort(__float2half(xv[2 * p + 1]));
        hi[p] = h0 | (h1 << 16);
    }
    u32 off = (u32)e * 144 + (u32)j0 * 2;
    *(uint4*)(sm + SM_A_HI + off)      = make_uint4(hi[0], hi[1], hi[2], hi[3]);
    *(uint4*)(sm + SM_A_HI + off + 16) = make_uint4(hi[4], hi[5], hi[6], hi[7]);
}

/* =================== edge kernel (warp-specialized) =============== */
__global__ void __launch_bounds__(256, 2)
edge_kernel(const float* __restrict__ nf,  const float* __restrict__ esh,
            const float* __restrict__ ebas, const int*  __restrict__ eidx,
            const float* __restrict__ W1,  const float* __restrict__ b1,
            const float* __restrict__ b2p, const float* __restrict__ b3p)
{
    extern __shared__ char sm[];
    const u32 sbv = s2u(sm);
    const int tid = threadIdx.x;
    const int wid = tid >> 5, lane = tid & 31;
    const int e = tid >> 2, q = tid & 3;
    const int ge = blockIdx.x * 64 + e;
    const bool active = ge < N_EDGES;
    int* sSrc = (int*)(sm + SM_SRC);
    int* sDst = (int*)(sm + SM_DST);

    /* ---- prologue (all 256 threads) ---- */
    if (tid < 128) ((float4*)(sm + SM_W1))[tid] = ((const float4*)W1)[tid];
    if (tid < 16)               ((float4*)(sm + SM_B1b))[tid]     = ((const float4*)b1)[tid];
    else if (tid < 32)          ((float4*)(sm + SM_B2))[tid - 16] = ((const float4*)b2p)[tid - 16];
    if (tid >= 32 && tid < 224) ((float4*)(sm + SM_B3))[tid - 32] = ((const float4*)b3p)[tid - 32];
#pragma unroll
    for (int s = 0; s < 2; s++) {                      /* B0 <- W2T, B1 <- W3 chunk 0 */
        int v = tid + s * 256;
        u32 doff = (u32)(v >> 3) * 144 + (u32)(v & 7) * 16;
        *(uint4*)(sm + SM_B0 + doff) = ((const uint4*)g_w2t_h)[v];
        *(uint4*)(sm + SM_B1 + doff) = ((const uint4*)g_w3t_h)[v];
    }
    if (q == 0) {
        float4 sh = active ? *(const float4*)(esh + (size_t)ge * 4) : make_float4(0, 0, 0, 0);
        ((float*)(sm + SM_SH0))[e] = sh.x;
        ((float*)(sm + SM_SH1))[e * 4 + 0] = sh.y;
        ((float*)(sm + SM_SH1))[e * 4 + 1] = sh.z;
        ((float*)(sm + SM_SH1))[e * 4 + 2] = sh.w;
        sSrc[e] = active ? eidx[ge] : 0;
        sDst[e] = active ? eidx[N_EDGES + ge] : 0;
    } else if (q == 1) {
        float4 bA = active ? *(const float4*)(ebas + (size_t)ge * 8)     : make_float4(0, 0, 0, 0);
        float4 bB = active ? *(const float4*)(ebas + (size_t)ge * 8 + 4) : make_float4(0, 0, 0, 0);
        float* bs = (float*)(sm + SM_BAS) + e * 9;
        bs[0] = bA.x; bs[1] = bA.y; bs[2] = bA.z; bs[3] = bA.w;
        bs[4] = bB.x; bs[5] = bB.y; bs[6] = bB.z; bs[7] = bB.w;
    }
    __syncthreads();

    {   /* gather node features + coefficients */
        const int src = sSrc[e];
        const float* nfr = nf + (size_t)src * 40;
        const float sh0 = ((float*)(sm + SM_SH0))[e];
        const float s1x = ((float*)(sm + SM_SH1))[e * 4 + 0];
        const float s1y = ((float*)(sm + SM_SH1))[e * 4 + 1];
        const float s1z = ((float*)(sm + SM_SH1))[e * 4 + 2];
        for (int u = q; u < 16; u += 4)
            ((float*)(sm + SM_SX))[e * 17 + u] = active ? nfr[u] : 0.f;
        for (int u = q; u < 8; u += 4) {
            float v0 = active ? nfr[16 + u * 3 + 0] : 0.f;
            float v1 = active ? nfr[16 + u * 3 + 1] : 0.f;
            float v2 = active ? nfr[16 + u * 3 + 2] : 0.f;
            float* vs = (float*)(sm + SM_VS);
            vs[e * 25 + u * 3 + 0] = v0 * sh0;
            vs[e * 25 + u * 3 + 1] = v1 * sh0;
            vs[e * 25 + u * 3 + 2] = v2 * sh0;
            ((float*)(sm + SM_CB))[e * 9 + u] = (v0 * s1x + v1 * s1y + v2 * s1z) * SQRT3_INV;
        }
    }

    {   /* H1 = silu(basis @ W1 + b1) -> A hi/lo (round 0 is 2-term) */
        const float* w1s = (const float*)(sm + SM_W1);
        const float* b1s = (const float*)(sm + SM_B1b);
        const float* bs  = (const float*)(sm + SM_BAS) + e * 9;
        float bk[8];
#pragma unroll
        for (int k = 0; k < 8; k++) bk[k] = bs[k];
        const int j0 = q * 16;
        float xv[16];
#pragma unroll
        for (int jj = 0; jj < 16; jj++) {
            float x = b1s[j0 + jj];
#pragma unroll
            for (int k = 0; k < 8; k++) x += bk[k] * w1s[k * 64 + j0 + jj];
            xv[jj] = silu_f(x);
        }
        split_store16(sm, e, j0, xv);
    }
    __syncthreads();

    if (wid < 4) {
        /* ========== PRODUCER: 2x2 warp tiling (M32 x N32 each) ===== */
        const int mi = wid & 1, ni = wid >> 1;
        const int m0 = mi * 32, n0 = ni * 32;
        const u32 arow = (u32)(m0 + ((lane >> 3) & 1) * 8 + (lane & 7)) * 144
                       + (u32)((lane >> 4) & 1) * 16;
        const u32 boffr = (u32)(((lane >> 4) & 1) * 8 + (lane & 7)) * 144
                        + (u32)((lane >> 3) & 1) * 16;
        const int cg = lane >> 2, c2 = (lane & 3) * 2;

        u32 ah[2][4][4];

        /* ---- round 0: P = H1 @ W2^T, 2-term; hi->P0, lo->P1 ---- */
        {
            u32 al[2][4][4];
#pragma unroll
            for (int mt = 0; mt < 2; mt++)
#pragma unroll
                for (int ks = 0; ks < 4; ks++) {
                    LDSM4(ah[mt][ks], sbv + SM_A_HI + arow + mt * 2304 + ks * 32);
                    LDSM4(al[mt][ks], sbv + SM_A_LO + arow + mt * 2304 + ks * 32);
                }
            float acc[2][4][4];
#pragma unroll
            for (int mt = 0; mt < 2; mt++)
#pragma unroll
                for (int nt = 0; nt < 4; nt++)
#pragma unroll
                    for (int i = 0; i < 4; i++) acc[mt][nt][i] = 0.f;
#pragma unroll
            for (int ks = 0; ks < 4; ks++) {
                u32 bh[8];
                LDSM4(&bh[0], sbv + SM_B0 + boffr + (u32)n0 * 144 + ks * 32);
                LDSM4(&bh[4], sbv + SM_B0 + boffr + (u32)(n0 + 16) * 144 + ks * 32);
#pragma unroll
                for (int mt = 0; mt < 2; mt++)
#pragma unroll
                    for (int nt = 0; nt < 4; nt++) {
                        MMA_F16(acc[mt][nt], ah[mt][ks], bh[nt * 2], bh[nt * 2 + 1]);
                        MMA_F16(acc[mt][nt], al[mt][ks], bh[nt * 2], bh[nt * 2 + 1]);
                    }
            }
            const float* bias = (const float*)(sm + SM_B2);
#pragma unroll
            for (int nt = 0; nt < 4; nt++) {
                const int col = n0 + nt * 8 + c2;
                float2 bv = *(const float2*)&bias[col];
#pragma unroll
                for (int mt = 0; mt < 2; mt++) {
                    const int row0 = m0 + mt * 16 + cg;
                    float v0 = acc[mt][nt][0] + bv.x, v1 = acc[mt][nt][1] + bv.y;
                    float v2 = acc[mt][nt][2] + bv.x, v3 = acc[mt][nt][3] + bv.y;
                    __half2 h01 = __floats2half2_rn(v0, v1);
                    __half2 h23 = __floats2half2_rn(v2, v3);
                    *(__half2*)(sm + SM_P0 + row0 * 144 + col * 2)       = h01;
                    *(__half2*)(sm + SM_P0 + (row0 + 8) * 144 + col * 2) = h23;
                    __half2 l01 = __floats2half2_rn(v0 - __low2float(h01), v1 - __high2float(h01));
                    __half2 l23 = __floats2half2_rn(v2 - __low2float(h23), v3 - __high2float(h23));
                    *(__half2*)(sm + SM_P1 + row0 * 144 + col * 2)       = l01;
                    *(__half2*)(sm + SM_P1 + (row0 + 8) * 144 + col * 2) = l23;
                }
            }
            BARA(1);                                 /* FULL0 */
            BARS(3);                                 /* EMPTY0: H2 in A smem */
#pragma unroll
            for (int mt = 0; mt < 2; mt++)
#pragma unroll
                for (int ks = 0; ks < 4; ks++)
                    LDSM4(ah[mt][ks], sbv + SM_A_HI + arow + mt * 2304 + ks * 32);
        }

        /* ---- rounds 1..12: single-term A (hi only) ---- */
#pragma unroll 1
        for (int r = 1; r <= 12; r++) {
            const int p = r & 1;
            if (r >= 3) BARS(3 + p);                 /* EMPTY[p] */
            const u32 baseB = sbv + (p ? SM_B1 : SM_B0);
            float acc[2][4][4];
#pragma unroll
            for (int mt = 0; mt < 2; mt++)
#pragma unroll
                for (int nt = 0; nt < 4; nt++)
#pragma unroll
                    for (int i = 0; i < 4; i++) acc[mt][nt][i] = 0.f;
#pragma unroll
            for (int ks = 0; ks < 4; ks++) {
                u32 bh[8];
                LDSM4(&bh[0], baseB + boffr + (u32)n0 * 144 + ks * 32);
                LDSM4(&bh[4], baseB + boffr + (u32)(n0 + 16) * 144 + ks * 32);
#pragma unroll
                for (int mt = 0; mt < 2; mt++)
#pragma unroll
                    for (int nt = 0; nt < 4; nt++)
                        MMA_F16(acc[mt][nt], ah[mt][ks], bh[nt * 2], bh[nt * 2 + 1]);
            }
            char* PB = sm + (p ? SM_P1 : SM_P0);
            const float* bias = (const float*)(sm + SM_B3) + (r - 1) * 64;
#pragma unroll
            for (int nt = 0; nt < 4; nt++) {
                const int col = n0 + nt * 8 + c2;
                float2 bv = *(const float2*)&bias[col];
#pragma unroll
                for (int mt = 0; mt < 2; mt++) {
                    const int row0 = m0 + mt * 16 + cg;
                    __half2 h01 = __floats2half2_rn(acc[mt][nt][0] + bv.x, acc[mt][nt][1] + bv.y);
                    __half2 h23 = __floats2half2_rn(acc[mt][nt][2] + bv.x, acc[mt][nt][3] + bv.y);
                    *(__half2*)(PB + row0 * 144 + col * 2)       = h01;
                    *(__half2*)(PB + (row0 + 8) * 144 + col * 2) = h23;
                }
            }
            BARA(1 + p);                             /* FULL[p] */
        }
    } else {
        /* =============== CONSUMER: warps 4-7 ======================= */
        const int tp = tid - 128;
        const int ce = tp >> 1, cq = tp & 1;
        const bool cact = (blockIdx.x * 64 + ce) < N_EDGES;
        const int eP = ce * 144;                     /* byte row offset in P */
        const u32 shx = (u32)cq * 16;                /* half-select shift */
        const float sh0e = ((const float*)(sm + SM_SH0))[ce];
        const float* sxs = (const float*)(sm + SM_SX) + ce * 17;
        const float* cbs = (const float*)(sm + SM_CB) + ce * 9;
        const float* vse = (const float*)(sm + SM_VS) + ce * 25;

        float rs[12], rtsv[4], rv[4][3];
#pragma unroll
        for (int k = 0; k < 12; k++) rs[k] = 0.f;
#pragma unroll
        for (int t = 0; t < 4; t++) {
            rtsv[t] = 0.f;
            rv[t][0] = 0.f; rv[t][1] = 0.f; rv[t][2] = 0.f;
        }

#pragma unroll
        for (int r = 0; r <= 12; r++) {
            BARS(1 + (r & 1));                       /* FULL[p] */
            if (r <= 10) {                           /* stage W3 chunk r+1 */
                char* dB = sm + ((r & 1) ? SM_B1 : SM_B0);
                const uint4* srcB = ((const uint4*)g_w3t_h) + (r + 1) * 512;
#pragma unroll
                for (int s = 0; s < 4; s++) {
                    int v = tp + s * 128;
                    u32 doff = (u32)(v >> 3) * 144 + (u32)(v & 7) * 16;
                    *(uint4*)(dB + doff) = srcB[v];
                }
            }
            if (r == 0) {
                /* H2 = silu(hi+lo) -> A hi only (single-term W3 rounds) */
                const int j0 = cq * 32;
                float xv[16];
#pragma unroll
                for (int half = 0; half < 2; half++) {
#pragma unroll
                    for (int jj = 0; jj < 16; jj += 2) {
                        const int c = j0 + half * 16 + jj;
                        float2 hf = __half22float2(*(const __half2*)(sm + SM_P0 + eP + c * 2));
                        float2 lf = __half22float2(*(const __half2*)(sm + SM_P1 + eP + c * 2));
                        xv[jj]     = silu_f(hf.x + lf.x);
                        xv[jj + 1] = silu_f(hf.y + lf.y);
                    }
                    store16_hi(sm, ce, j0 + half * 16, xv);
                }
                BARA(3);                             /* EMPTY0: after H2 + P1-lo read */
            } else {
                const char* PB = sm + ((r & 1) ? SM_P1 : SM_P0);
                /* vector-load whole P row into regs */
                u32 row[32];
#pragma unroll
                for (int i = 0; i < 8; i++) {
                    uint4 v4 = *(const uint4*)(PB + eP + i * 16);
                    row[i * 4 + 0] = v4.x; row[i * 4 + 1] = v4.y;
                    row[i * 4 + 2] = v4.z; row[i * 4 + 3] = v4.w;
                }
                /* early release: P row is in regs, B staging done */
                if (r <= 10) BARA(3 + (r & 1));      /* EMPTY[p] */
                const int cc = r - 1;
                if (cc < 9) {                        /* SS (cc<6) or VV */
                    const bool isSS = (cc < 6);
                    const int base = cc * 64;
                    const int sub = isSS ? 0 : 384;
                    const int bm2 = (base % 24) / 2;     /* 0,8,4,... */
                    const int d = (base - sub) / 24;
                    const float* coef = isSS ? sxs : cbs;
#pragma unroll
                    for (int k = 0; k < 12; k++) {
                        const int m = (k - bm2 + 12) % 12;   /* compile-time */
                        const int u0 = d + ((k < bm2) ? 1 : 0);
                        float a = hsel(row[m], shx) * coef[u0]
                                + hsel(row[m + 12], shx) * coef[u0 + 1];
                        if (m < 8)
                            a += hsel(row[m + 24], shx) * coef[u0 + 2];
                        rs[k] += isSS ? a * sh0e : a;
                    }
                } else if (cc < 11) {                /* SV */
                    const int uoff = (cc == 9) ? 0 : 8;
#pragma unroll
                    for (int t = 0; t < 4; t++) {
                        float a = 0.f;
#pragma unroll
                        for (int u = 0; u < 8; u++)
                            a += hsel(row[u * 4 + t], shx) * sxs[uoff + u];
                        rtsv[t] += a;
                    }
                } else {                             /* VS */
#pragma unroll
                    for (int t = 0; t < 4; t++) {
                        float pv[8];
#pragma unroll
                        for (int u = 0; u < 8; u++)
                            pv[u] = hsel(row[u * 4 + t], shx);
#pragma unroll
                        for (int i = 0; i < 3; i++) {
                            float a = 0.f;
#pragma unroll
                            for (int u = 0; u < 8; u++) a += pv[u] * vse[u * 3 + i];
                            rv[t][i] += a;
                        }
                    }
                }
            }
        }

        /* ---- finalize + scatter ---- */
        if (cact) {
            const int dst = sDst[ce];
            const float* sh1 = (const float*)(sm + SM_SH1) + ce * 4;
            float* ap = &g_agg[(size_t)dst * 48];
#pragma unroll
            for (int k = 0; k < 12; k++)
                atomicAdd(ap + cq + 2 * k, rs[k] * ALPHA_C);
#pragma unroll
            for (int t = 0; t < 4; t++) {
                const int w = cq + 2 * t;
#pragma unroll
                for (int i = 0; i < 3; i++)
                    atomicAdd(ap + 24 + w * 3 + i, (rv[t][i] + rtsv[t] * sh1[i]) * ALPHA_C);
            }
        }
    }
}

/* =================== node post-processing ========================= */
__global__ void zero_agg_kernel()
{
    int i = blockIdx.x * blockDim.x + threadIdx.x;
    if (i < N_NODES * 48) g_agg[i] = 0.f;
}
__global__ void zero_stats_kernel()
{
    if (threadIdx.x < 40) g_stats[threadIdx.x] = 0.f;
}

__global__ void node_kernel(const float* __restrict__ si_w0, const float* __restrict__ si_w1)
{
    __shared__ float w0[256], w1[64];
    int tid = threadIdx.x;
    if (tid < 256) w0[tid] = si_w0[tid] * 0.25f;
    if (tid < 64)  w1[tid] = si_w1[tid] * 0.35355339059327373f;
    __syncthreads();
    int n = blockIdx.x * blockDim.x + tid;
    if (n >= N_NODES) return;
    const float* a = &g_agg[(size_t)n * 48];
    float s[16], v[24];
#pragma unroll
    for (int u = 0; u < 16; u++) s[u] = silu_f(a[u]);
#pragma unroll
    for (int u = 0; u < 8; u++) {
        float g = sigmoid_f(a[16 + u]);
        v[u * 3 + 0] = a[24 + u * 3 + 0] * g;
        v[u * 3 + 1] = a[24 + u * 3 + 1] * g;
        v[u * 3 + 2] = a[24 + u * 3 + 2] * g;
    }
    float out[40];
#pragma unroll
    for (int w = 0; w < 16; w++) {
        float acc = 0.f;
#pragma unroll
        for (int u = 0; u < 16; u++) acc += s[u] * w0[u * 16 + w];
        out[w] = acc;
    }
#pragma unroll
    for (int w = 0; w < 8; w++) {
#pragma unroll
        for (int i = 0; i < 3; i++) {
            float acc = 0.f;
#pragma unroll
            for (int u = 0; u < 8; u++) acc += v[u * 3 + i] * w1[u * 8 + w];
            out[16 + w * 3 + i] = acc;
        }
    }
#pragma unroll
    for (int i = 0; i < 40; i += 4)
        *(float4*)&g_tmp[(size_t)n * 40 + i] = make_float4(out[i], out[i + 1], out[i + 2], out[i + 3]);
}

__global__ void stats_kernel()
{
    __shared__ float red[8 * 40];
    float acc[40];
#pragma unroll
    for (int i = 0; i < 40; i++) acc[i] = 0.f;
    for (int n = blockIdx.x * blockDim.x + threadIdx.x; n < N_NODES;
         n += gridDim.x * blockDim.x) {
        const float* t = &g_tmp[(size_t)n * 40];
#pragma unroll
        for (int c = 0; c < 16; c++) { float x = t[c]; acc[c] += x; acc[16 + c] += x * x; }
#pragma unroll
        for (int w = 0; w < 8; w++) {
            float x0 = t[16 + w * 3], x1 = t[17 + w * 3], x2 = t[18 + w * 3];
            acc[32 + w] += x0 * x0 + x1 * x1 + x2 * x2;
        }
    }
#pragma unroll
    for (int i = 0; i < 40; i++)
        for (int o = 16; o > 0; o >>= 1)
            acc[i] += __shfl_down_sync(0xffffffff, acc[i], o);
    int warp = threadIdx.x >> 5, lane = threadIdx.x & 31;
    if (lane == 0)
        for (int i = 0; i < 40; i++) red[warp * 40 + i] = acc[i];
    __syncthreads();
    if (threadIdx.x < 40) {
        float t = 0.f;
#pragma unroll
        for (int w = 0; w < 8; w++) t += red[w * 40 + threadIdx.x];
        atomicAdd(&g_stats[threadIdx.x], t);
    }
}

__global__ void finalize_kernel(const float* __restrict__ nf,
                                const float* __restrict__ bn_ws,
                                const float* __restrict__ bn_bs,
                                const float* __restrict__ bn_wv,
                                float* __restrict__ out)
{
    int t = blockIdx.x * blockDim.x + threadIdx.x;
    if (t >= N_NODES * 40) return;
    int c = t % 40;
    float val = g_tmp[t];
    const float invN = 1.f / (float)N_NODES;
    if (c < 16) {
        float m   = g_stats[c] * invN;
        float var = g_stats[16 + c] * invN - m * m;
        val = (val - m) * rsqrtf(var + BN_EPS) * bn_ws[c] + bn_bs[c];
    } else {
        int w = (c - 16) / 3;
        float vn = g_stats[32 + w] * (invN * (1.f / 3.f));
        val = val * rsqrtf(vn + BN_EPS) * bn_wv[w];
    }
    out[t] = val + nf[t];
}

/* ============================ launch ============================== */
extern "C" void kernel_launch(void* const* d_in, const int* in_sizes, int n_in,
                              void* d_out, int out_size)
{
    const float* nf    = (const float*)d_in[0];
    const float* esh   = (const float*)d_in[1];
    const float* ebas  = (const float*)d_in[2];
    const int*   eidx  = (const int*)  d_in[3];
    const float* W1    = (const float*)d_in[4];
    const float* b1    = (const float*)d_in[5];
    const float* W2    = (const float*)d_in[6];
    const float* b2    = (const float*)d_in[7];
    const float* W3    = (const float*)d_in[8];
    const float* b3    = (const float*)d_in[9];
    const float* si_w0 = (const float*)d_in[10];
    const float* si_w1 = (const float*)d_in[11];
    const float* bn_ws = (const float*)d_in[12];
    const float* bn_bs = (const float*)d_in[13];
    const float* bn_wv = (const float*)d_in[14];
    float* out = (float*)d_out;

    cudaFuncSetAttribute(edge_kernel, cudaFuncAttributeMaxDynamicSharedMemorySize, SM_TOTAL);

    /* launch order keeps edge_kernel at 0-indexed launch 3 (ncu slot) */
    prep_kernel<<<192, 256>>>(W2, W3);
    zero_agg_kernel<<<(N_NODES * 48 + 255) / 256, 256>>>();
    zero_stats_kernel<<<1, 64>>>();
    edge_kernel<<<(N_EDGES + 63) / 64, 256, SM_TOTAL>>>(nf, esh, ebas, eidx, W1, b1, b2, b3);
    node_kernel<<<(N_NODES + 255) / 256, 256>>>(si_w0, si_w1);
    stats_kernel<<<120, 256>>>();
    finalize_kernel<<<(N_NODES * 40 + 255) / 256, 256>>>(nf, bn_ws, bn_bs, bn_wv, out);
}

// round 15
// speedup vs baseline: 1.3751x; 1.0678x over previous
#include <cuda_runtime.h>
#include <cuda_fp16.h>

#define N_NODES 50000
#define N_EDGES 300000
#define SQRT3_INV 0.57735026918962576451f
#define ALPHA_C   0.20412414523193150818f   /* 1/sqrt(24) */
#define BN_EPS    1e-5f

typedef unsigned int u32;

/* ---------------- scratch (no allocation allowed) ---------------- */
__device__ float g_agg[N_NODES * 48];
__device__ float g_tmp[N_NODES * 40];
__device__ float g_stats[40];
__device__ __half g_w2t_h[64 * 64];      /* [n][k] transposed, fp16 */
__device__ __half g_w3t_h[768 * 64];     /* [w][k] transposed, fp16 */

__device__ __forceinline__ float silu_f(float x)    { return x / (1.f + __expf(-x)); }
__device__ __forceinline__ float sigmoid_f(float x) { return 1.f / (1.f + __expf(-x)); }

__device__ __forceinline__ u32 s2u(const void* p) {
    u32 a;
    asm("{ .reg .u64 t; cvta.to.shared.u64 t, %1; cvt.u32.u64 %0, t; }" : "=r"(a) : "l"(p));
    return a;
}
__device__ __forceinline__ void f16split(float x, u32& h, u32& l) {
    __half hb = __float2half(x);
    __half lb = __float2half(x - __half2float(hb));
    h = (u32)__half_as_ushort(hb);
    l = (u32)__half_as_ushort(lb);
}
/* extract fp16 (low/high per sh=0/16) from packed u32, to fp32 */
__device__ __forceinline__ float hsel(u32 v, u32 sh) {
    return __half2float(__ushort_as_half((unsigned short)(v >> sh)));
}

#define LDSM4(R, ADDR) \
    asm volatile("ldmatrix.sync.aligned.m8n8.x4.shared.b16 {%0,%1,%2,%3}, [%4];" \
        : "=r"((R)[0]), "=r"((R)[1]), "=r"((R)[2]), "=r"((R)[3]) : "r"(ADDR))

#define MMA_F16(C, A, B0, B1) \
    asm volatile("mma.sync.aligned.m16n8k16.row.col.f32.f16.f16.f32 " \
        "{%0,%1,%2,%3}, {%4,%5,%6,%7}, {%8,%9}, {%0,%1,%2,%3};" \
        : "+f"((C)[0]), "+f"((C)[1]), "+f"((C)[2]), "+f"((C)[3]) \
        : "r"((A)[0]), "r"((A)[1]), "r"((A)[2]), "r"((A)[3]), "r"(B0), "r"(B1))

/* named barriers: FULL[p] = 1+p, EMPTY[p] = 3+p */
#define BARS(id) asm volatile("bar.sync %0, 256;"   :: "r"(id) : "memory")
#define BARA(id) asm volatile("bar.arrive %0, 256;" :: "r"(id) : "memory")

/* ---------------- smem layout (bytes); rows padded to 72 halves --- */
constexpr int SM_A_HI = 0;         /* 64 x 144B */
constexpr int SM_A_LO = 9216;
constexpr int SM_B0   = 18432;     /* 64 x 144B, fp16 */
constexpr int SM_B1   = 27648;
constexpr int SM_P0   = 36864;     /* 64 x 144B, fp16 (72-half rows) */
constexpr int SM_P1   = 46080;
constexpr int SM_B2   = 55296;     /* 64 f   */
constexpr int SM_B3   = 55552;     /* 768 f  */
constexpr int SM_SH0  = 58624;     /* 64 f   */
constexpr int SM_SH1  = 58880;     /* 64x4 f */
constexpr int SM_SX   = 59904;     /* 64x17 f */
constexpr int SM_CB   = 64256;     /* 64x9 f */
constexpr int SM_VS   = 66560;     /* 64x25 f */
constexpr int SM_SRC  = 72960;     /* 64 int */
constexpr int SM_DST  = 73216;     /* 64 int */
constexpr int SM_TOTAL = 73472;    /* 71.75 KB -> 3 CTAs/SM */
/* prologue-only arrays aliased into P0 (dead until round-0 output) */
constexpr int SM_W1  = SM_P0;          /* 512 f  */
constexpr int SM_B1b = SM_P0 + 2048;   /* 64 f   */
constexpr int SM_BAS = SM_P0 + 2304;   /* 64x9 f */

/* ============ prep: transpose W2, W3 to fp16 ====================== */
__global__ void prep_kernel(const float* __restrict__ W2, const float* __restrict__ W3)
{
    int i = blockIdx.x * 256 + threadIdx.x;
    if (i < 64 * 64) {
        int n = i >> 6, k = i & 63;
        g_w2t_h[i] = __float2half(W2[k * 64 + n]);
    }
    if (i < 768 * 64) {
        int w = i >> 6, k = i & 63;
        g_w3t_h[i] = __float2half(W3[k * 768 + w]);
    }
}

/* split 16 fp32 -> fp16 hi/lo pairs, store one A row segment         */
__device__ __forceinline__ void split_store16(char* sm, int e, int j0, const float* xv)
{
    u32 hi[8], lo[8];
#pragma unroll
    for (int p = 0; p < 8; p++) {
        u32 h0, l0, h1, l1;
        f16split(xv[2 * p], h0, l0);
        f16split(xv[2 * p + 1], h1, l1);
        hi[p] = h0 | (h1 << 16);
        lo[p] = l0 | (l1 << 16);
    }
    u32 off = (u32)e * 144 + (u32)j0 * 2;
    *(uint4*)(sm + SM_A_HI + off)      = make_uint4(hi[0], hi[1], hi[2], hi[3]);
    *(uint4*)(sm + SM_A_HI + off + 16) = make_uint4(hi[4], hi[5], hi[6], hi[7]);
    *(uint4*)(sm + SM_A_LO + off)      = make_uint4(lo[0], lo[1], lo[2], lo[3]);
    *(uint4*)(sm + SM_A_LO + off + 16) = make_uint4(lo[4], lo[5], lo[6], lo[7]);
}

/* hi-only variant (H2 single-term A path)                            */
__device__ __forceinline__ void store16_hi(char* sm, int e, int j0, const float* xv)
{
    u32 hi[8];
#pragma unroll
    for (int p = 0; p < 8; p++) {
        u32 h0 = (u32)__half_as_ushort(__float2half(xv[2 * p]));
        u32 h1 = (u32)__half_as_ushort(__float2half(xv[2 * p + 1]));
        hi[p] = h0 | (h1 << 16);
    }
    u32 off = (u32)e * 144 + (u32)j0 * 2;
    *(uint4*)(sm + SM_A_HI + off)      = make_uint4(hi[0], hi[1], hi[2], hi[3]);
    *(uint4*)(sm + SM_A_HI + off + 16) = make_uint4(hi[4], hi[5], hi[6], hi[7]);
}

/* =================== edge kernel (warp-specialized) =============== */
__global__ void __launch_bounds__(256, 3)
edge_kernel(const float* __restrict__ nf,  const float* __restrict__ esh,
            const float* __restrict__ ebas, const int*  __restrict__ eidx,
            const float* __restrict__ W1,  const float* __restrict__ b1,
            const float* __restrict__ b2p, const float* __restrict__ b3p)
{
    extern __shared__ char sm[];
    const u32 sbv = s2u(sm);
    const int tid = threadIdx.x;
    const int wid = tid >> 5, lane = tid & 31;
    const int e = tid >> 2, q = tid & 3;
    const int ge = blockIdx.x * 64 + e;
    const bool active = ge < N_EDGES;
    int* sSrc = (int*)(sm + SM_SRC);
    int* sDst = (int*)(sm + SM_DST);

    /* ---- prologue (all 256 threads) ---- */
    if (tid < 128) ((float4*)(sm + SM_W1))[tid] = ((const float4*)W1)[tid];
    if (tid < 16)               ((float4*)(sm + SM_B1b))[tid]     = ((const float4*)b1)[tid];
    else if (tid < 32)          ((float4*)(sm + SM_B2))[tid - 16] = ((const float4*)b2p)[tid - 16];
    if (tid >= 32 && tid < 224) ((float4*)(sm + SM_B3))[tid - 32] = ((const float4*)b3p)[tid - 32];
#pragma unroll
    for (int s = 0; s < 2; s++) {                      /* B0 <- W2T, B1 <- W3 chunk 0 */
        int v = tid + s * 256;
        u32 doff = (u32)(v >> 3) * 144 + (u32)(v & 7) * 16;
        *(uint4*)(sm + SM_B0 + doff) = ((const uint4*)g_w2t_h)[v];
        *(uint4*)(sm + SM_B1 + doff) = ((const uint4*)g_w3t_h)[v];
    }
    if (q == 0) {
        float4 sh = active ? *(const float4*)(esh + (size_t)ge * 4) : make_float4(0, 0, 0, 0);
        ((float*)(sm + SM_SH0))[e] = sh.x;
        ((float*)(sm + SM_SH1))[e * 4 + 0] = sh.y;
        ((float*)(sm + SM_SH1))[e * 4 + 1] = sh.z;
        ((float*)(sm + SM_SH1))[e * 4 + 2] = sh.w;
        sSrc[e] = active ? eidx[ge] : 0;
        sDst[e] = active ? eidx[N_EDGES + ge] : 0;
    } else if (q == 1) {
        float4 bA = active ? *(const float4*)(ebas + (size_t)ge * 8)     : make_float4(0, 0, 0, 0);
        float4 bB = active ? *(const float4*)(ebas + (size_t)ge * 8 + 4) : make_float4(0, 0, 0, 0);
        float* bs = (float*)(sm + SM_BAS) + e * 9;
        bs[0] = bA.x; bs[1] = bA.y; bs[2] = bA.z; bs[3] = bA.w;
        bs[4] = bB.x; bs[5] = bB.y; bs[6] = bB.z; bs[7] = bB.w;
    }
    __syncthreads();

    {   /* gather node features + coefficients */
        const int src = sSrc[e];
        const float* nfr = nf + (size_t)src * 40;
        const float sh0 = ((float*)(sm + SM_SH0))[e];
        const float s1x = ((float*)(sm + SM_SH1))[e * 4 + 0];
        const float s1y = ((float*)(sm + SM_SH1))[e * 4 + 1];
        const float s1z = ((float*)(sm + SM_SH1))[e * 4 + 2];
        for (int u = q; u < 16; u += 4)
            ((float*)(sm + SM_SX))[e * 17 + u] = active ? nfr[u] : 0.f;
        for (int u = q; u < 8; u += 4) {
            float v0 = active ? nfr[16 + u * 3 + 0] : 0.f;
            float v1 = active ? nfr[16 + u * 3 + 1] : 0.f;
            float v2 = active ? nfr[16 + u * 3 + 2] : 0.f;
            float* vs = (float*)(sm + SM_VS);
            vs[e * 25 + u * 3 + 0] = v0 * sh0;
            vs[e * 25 + u * 3 + 1] = v1 * sh0;
            vs[e * 25 + u * 3 + 2] = v2 * sh0;
            ((float*)(sm + SM_CB))[e * 9 + u] = (v0 * s1x + v1 * s1y + v2 * s1z) * SQRT3_INV;
        }
    }

    {   /* H1 = silu(basis @ W1 + b1) -> A hi/lo (round 0 is 2-term) */
        const float* w1s = (const float*)(sm + SM_W1);
        const float* b1s = (const float*)(sm + SM_B1b);
        const float* bs  = (const float*)(sm + SM_BAS) + e * 9;
        float bk[8];
#pragma unroll
        for (int k = 0; k < 8; k++) bk[k] = bs[k];
        const int j0 = q * 16;
        float xv[16];
#pragma unroll
        for (int jj = 0; jj < 16; jj++) {
            float x = b1s[j0 + jj];
#pragma unroll
            for (int k = 0; k < 8; k++) x += bk[k] * w1s[k * 64 + j0 + jj];
            xv[jj] = silu_f(x);
        }
        split_store16(sm, e, j0, xv);
    }
    __syncthreads();

    if (wid < 4) {
        /* ========== PRODUCER: 2x2 warp tiling (M32 x N32 each) ===== */
        const int mi = wid & 1, ni = wid >> 1;
        const int m0 = mi * 32, n0 = ni * 32;
        const u32 arow = (u32)(m0 + ((lane >> 3) & 1) * 8 + (lane & 7)) * 144
                       + (u32)((lane >> 4) & 1) * 16;
        const u32 boffr = (u32)(((lane >> 4) & 1) * 8 + (lane & 7)) * 144
                        + (u32)((lane >> 3) & 1) * 16;
        const int cg = lane >> 2, c2 = (lane & 3) * 2;

        /* ---- round 0: P = H1 @ W2^T, 2-term; hi->P0, lo->P1 ---- */
        {
            float acc[2][4][4];
#pragma unroll
            for (int mt = 0; mt < 2; mt++)
#pragma unroll
                for (int nt = 0; nt < 4; nt++)
#pragma unroll
                    for (int i = 0; i < 4; i++) acc[mt][nt][i] = 0.f;
#pragma unroll
            for (int ks = 0; ks < 4; ks++) {
                u32 ah0[4], ah1[4], al0[4], al1[4], bh[8];
                LDSM4(ah0, sbv + SM_A_HI + arow + ks * 32);
                LDSM4(ah1, sbv + SM_A_HI + arow + 2304 + ks * 32);
                LDSM4(al0, sbv + SM_A_LO + arow + ks * 32);
                LDSM4(al1, sbv + SM_A_LO + arow + 2304 + ks * 32);
                LDSM4(&bh[0], sbv + SM_B0 + boffr + (u32)n0 * 144 + ks * 32);
                LDSM4(&bh[4], sbv + SM_B0 + boffr + (u32)(n0 + 16) * 144 + ks * 32);
#pragma unroll
                for (int nt = 0; nt < 4; nt++) {
                    MMA_F16(acc[0][nt], ah0, bh[nt * 2], bh[nt * 2 + 1]);
                    MMA_F16(acc[0][nt], al0, bh[nt * 2], bh[nt * 2 + 1]);
                    MMA_F16(acc[1][nt], ah1, bh[nt * 2], bh[nt * 2 + 1]);
                    MMA_F16(acc[1][nt], al1, bh[nt * 2], bh[nt * 2 + 1]);
                }
            }
            const float* bias = (const float*)(sm + SM_B2);
#pragma unroll
            for (int nt = 0; nt < 4; nt++) {
                const int col = n0 + nt * 8 + c2;
                float2 bv = *(const float2*)&bias[col];
#pragma unroll
                for (int mt = 0; mt < 2; mt++) {
                    const int row0 = m0 + mt * 16 + cg;
                    float v0 = acc[mt][nt][0] + bv.x, v1 = acc[mt][nt][1] + bv.y;
                    float v2 = acc[mt][nt][2] + bv.x, v3 = acc[mt][nt][3] + bv.y;
                    __half2 h01 = __floats2half2_rn(v0, v1);
                    __half2 h23 = __floats2half2_rn(v2, v3);
                    *(__half2*)(sm + SM_P0 + row0 * 144 + col * 2)       = h01;
                    *(__half2*)(sm + SM_P0 + (row0 + 8) * 144 + col * 2) = h23;
                    __half2 l01 = __floats2half2_rn(v0 - __low2float(h01), v1 - __high2float(h01));
                    __half2 l23 = __floats2half2_rn(v2 - __low2float(h23), v3 - __high2float(h23));
                    *(__half2*)(sm + SM_P1 + row0 * 144 + col * 2)       = l01;
                    *(__half2*)(sm + SM_P1 + (row0 + 8) * 144 + col * 2) = l23;
                }
            }
            BARA(1);                                 /* FULL0 */
            BARS(3);                                 /* EMPTY0: H2 in A smem */
        }

        /* ---- rounds 1..12: single-term A (hi only) ---- */
#pragma unroll 1
        for (int r = 1; r <= 12; r++) {
            const int p = r & 1;
            if (r >= 3) BARS(3 + p);                 /* EMPTY[p] */
            const u32 baseB = sbv + (p ? SM_B1 : SM_B0);
            float acc[2][4][4];
#pragma unroll
            for (int mt = 0; mt < 2; mt++)
#pragma unroll
                for (int nt = 0; nt < 4; nt++)
#pragma unroll
                    for (int i = 0; i < 4; i++) acc[mt][nt][i] = 0.f;
#pragma unroll
            for (int ks = 0; ks < 4; ks++) {
                u32 ah0[4], ah1[4], bh[8];
                LDSM4(ah0, sbv + SM_A_HI + arow + ks * 32);
                LDSM4(ah1, sbv + SM_A_HI + arow + 2304 + ks * 32);
                LDSM4(&bh[0], baseB + boffr + (u32)n0 * 144 + ks * 32);
                LDSM4(&bh[4], baseB + boffr + (u32)(n0 + 16) * 144 + ks * 32);
#pragma unroll
                for (int nt = 0; nt < 4; nt++) {
                    MMA_F16(acc[0][nt], ah0, bh[nt * 2], bh[nt * 2 + 1]);
                    MMA_F16(acc[1][nt], ah1, bh[nt * 2], bh[nt * 2 + 1]);
                }
            }
            char* PB = sm + (p ? SM_P1 : SM_P0);
            const float* bias = (const float*)(sm + SM_B3) + (r - 1) * 64;
#pragma unroll
            for (int nt = 0; nt < 4; nt++) {
                const int col = n0 + nt * 8 + c2;
                float2 bv = *(const float2*)&bias[col];
#pragma unroll
                for (int mt = 0; mt < 2; mt++) {
                    const int row0 = m0 + mt * 16 + cg;
                    __half2 h01 = __floats2half2_rn(acc[mt][nt][0] + bv.x, acc[mt][nt][1] + bv.y);
                    __half2 h23 = __floats2half2_rn(acc[mt][nt][2] + bv.x, acc[mt][nt][3] + bv.y);
                    *(__half2*)(PB + row0 * 144 + col * 2)       = h01;
                    *(__half2*)(PB + (row0 + 8) * 144 + col * 2) = h23;
                }
            }
            BARA(1 + p);                             /* FULL[p] */
        }
    } else {
        /* =============== CONSUMER: warps 4-7 ======================= */
        const int tp = tid - 128;
        const int ce = tp >> 1, cq = tp & 1;
        const bool cact = (blockIdx.x * 64 + ce) < N_EDGES;
        const int eP = ce * 144;                     /* byte row offset in P */
        const u32 shx = (u32)cq * 16;                /* half-select shift */
        const float sh0e = ((const float*)(sm + SM_SH0))[ce];
        const float* sxs = (const float*)(sm + SM_SX) + ce * 17;
        const float* cbs = (const float*)(sm + SM_CB) + ce * 9;
        const float* vse = (const float*)(sm + SM_VS) + ce * 25;

        float rs[12], rtsv[4], rv[4][3];
#pragma unroll
        for (int k = 0; k < 12; k++) rs[k] = 0.f;
#pragma unroll
        for (int t = 0; t < 4; t++) {
            rtsv[t] = 0.f;
            rv[t][0] = 0.f; rv[t][1] = 0.f; rv[t][2] = 0.f;
        }

#pragma unroll
        for (int r = 0; r <= 12; r++) {
            BARS(1 + (r & 1));                       /* FULL[p] */
            if (r <= 10) {                           /* stage W3 chunk r+1 */
                char* dB = sm + ((r & 1) ? SM_B1 : SM_B0);
                const uint4* srcB = ((const uint4*)g_w3t_h) + (r + 1) * 512;
#pragma unroll
                for (int s = 0; s < 4; s++) {
                    int v = tp + s * 128;
                    u32 doff = (u32)(v >> 3) * 144 + (u32)(v & 7) * 16;
                    *(uint4*)(dB + doff) = srcB[v];
                }
            }
            if (r == 0) {
                /* H2 = silu(hi+lo) -> A hi only (single-term W3 rounds) */
                const int j0 = cq * 32;
                float xv[16];
#pragma unroll
                for (int half = 0; half < 2; half++) {
#pragma unroll
                    for (int jj = 0; jj < 16; jj += 2) {
                        const int c = j0 + half * 16 + jj;
                        float2 hf = __half22float2(*(const __half2*)(sm + SM_P0 + eP + c * 2));
                        float2 lf = __half22float2(*(const __half2*)(sm + SM_P1 + eP + c * 2));
                        xv[jj]     = silu_f(hf.x + lf.x);
                        xv[jj + 1] = silu_f(hf.y + lf.y);
                    }
                    store16_hi(sm, ce, j0 + half * 16, xv);
                }
                BARA(3);                             /* EMPTY0: after H2 + P1-lo read */
            } else {
                const char* PB = sm + ((r & 1) ? SM_P1 : SM_P0);
                /* vector-load whole P row into regs */
                u32 row[32];
#pragma unroll
                for (int i = 0; i < 8; i++) {
                    uint4 v4 = *(const uint4*)(PB + eP + i * 16);
                    row[i * 4 + 0] = v4.x; row[i * 4 + 1] = v4.y;
                    row[i * 4 + 2] = v4.z; row[i * 4 + 3] = v4.w;
                }
                /* early release: P row is in regs, B staging done */
                if (r <= 10) BARA(3 + (r & 1));      /* EMPTY[p] */
                const int cc = r - 1;
                if (cc < 9) {                        /* SS (cc<6) or VV */
                    const bool isSS = (cc < 6);
                    const int base = cc * 64;
                    const int sub = isSS ? 0 : 384;
                    const int bm2 = (base % 24) / 2;     /* 0,8,4,... */
                    const int d = (base - sub) / 24;
                    const float* coef = isSS ? sxs : cbs;
#pragma unroll
                    for (int k = 0; k < 12; k++) {
                        const int m = (k - bm2 + 12) % 12;   /* compile-time */
                        const int u0 = d + ((k < bm2) ? 1 : 0);
                        float a = hsel(row[m], shx) * coef[u0]
                                + hsel(row[m + 12], shx) * coef[u0 + 1];
                        if (m < 8)
                            a += hsel(row[m + 24], shx) * coef[u0 + 2];
                        rs[k] += isSS ? a * sh0e : a;
                    }
                } else if (cc < 11) {                /* SV */
                    const int uoff = (cc == 9) ? 0 : 8;
#pragma unroll
                    for (int t = 0; t < 4; t++) {
                        float a = 0.f;
#pragma unroll
                        for (int u = 0; u < 8; u++)
                            a += hsel(row[u * 4 + t], shx) * sxs[uoff + u];
                        rtsv[t] += a;
                    }
                } else {                             /* VS */
#pragma unroll
                    for (int t = 0; t < 4; t++) {
                        float pv[8];
#pragma unroll
                        for (int u = 0; u < 8; u++)
                            pv[u] = hsel(row[u * 4 + t], shx);
#pragma unroll
                        for (int i = 0; i < 3; i++) {
                            float a = 0.f;
#pragma unroll
                            for (int u = 0; u < 8; u++) a += pv[u] * vse[u * 3 + i];
                            rv[t][i] += a;
                        }
                    }
                }
            }
        }

        /* ---- finalize + scatter ---- */
        if (cact) {
            const int dst = sDst[ce];
            const float* sh1 = (const float*)(sm + SM_SH1) + ce * 4;
            float* ap = &g_agg[(size_t)dst * 48];
#pragma unroll
            for (int k = 0; k < 12; k++)
                atomicAdd(ap + cq + 2 * k, rs[k] * ALPHA_C);
#pragma unroll
            for (int t = 0; t < 4; t++) {
                const int w = cq + 2 * t;
#pragma unroll
                for (int i = 0; i < 3; i++)
                    atomicAdd(ap + 24 + w * 3 + i, (rv[t][i] + rtsv[t] * sh1[i]) * ALPHA_C);
            }
        }
    }
}

/* =================== node post-processing ========================= */
__global__ void zero_agg_kernel()
{
    int i = blockIdx.x * blockDim.x + threadIdx.x;
    if (i < N_NODES * 48) g_agg[i] = 0.f;
}
__global__ void zero_stats_kernel()
{
    if (threadIdx.x < 40) g_stats[threadIdx.x] = 0.f;
}

__global__ void node_kernel(const float* __restrict__ si_w0, const float* __restrict__ si_w1)
{
    __shared__ float w0[256], w1[64];
    int tid = threadIdx.x;
    if (tid < 256) w0[tid] = si_w0[tid] * 0.25f;
    if (tid < 64)  w1[tid] = si_w1[tid] * 0.35355339059327373f;
    __syncthreads();
    int n = blockIdx.x * blockDim.x + tid;
    if (n >= N_NODES) return;
    const float* a = &g_agg[(size_t)n * 48];
    float s[16], v[24];
#pragma unroll
    for (int u = 0; u < 16; u++) s[u] = silu_f(a[u]);
#pragma unroll
    for (int u = 0; u < 8; u++) {
        float g = sigmoid_f(a[16 + u]);
        v[u * 3 + 0] = a[24 + u * 3 + 0] * g;
        v[u * 3 + 1] = a[24 + u * 3 + 1] * g;
        v[u * 3 + 2] = a[24 + u * 3 + 2] * g;
    }
    float out[40];
#pragma unroll
    for (int w = 0; w < 16; w++) {
        float acc = 0.f;
#pragma unroll
        for (int u = 0; u < 16; u++) acc += s[u] * w0[u * 16 + w];
        out[w] = acc;
    }
#pragma unroll
    for (int w = 0; w < 8; w++) {
#pragma unroll
        for (int i = 0; i < 3; i++) {
            float acc = 0.f;
#pragma unroll
            for (int u = 0; u < 8; u++) acc += v[u * 3 + i] * w1[u * 8 + w];
            out[16 + w * 3 + i] = acc;
        }
    }
#pragma unroll
    for (int i = 0; i < 40; i += 4)
        *(float4*)&g_tmp[(size_t)n * 40 + i] = make_float4(out[i], out[i + 1], out[i + 2], out[i + 3]);
}

__global__ void stats_kernel()
{
    __shared__ float red[8 * 40];
    float acc[40];
#pragma unroll
    for (int i = 0; i < 40; i++) acc[i] = 0.f;
    for (int n = blockIdx.x * blockDim.x + threadIdx.x; n < N_NODES;
         n += gridDim.x * blockDim.x) {
        const float* t = &g_tmp[(size_t)n * 40];
#pragma unroll
        for (int c = 0; c < 16; c++) { float x = t[c]; acc[c] += x; acc[16 + c] += x * x; }
#pragma unroll
        for (int w = 0; w < 8; w++) {
            float x0 = t[16 + w * 3], x1 = t[17 + w * 3], x2 = t[18 + w * 3];
            acc[32 + w] += x0 * x0 + x1 * x1 + x2 * x2;
        }
    }
#pragma unroll
    for (int i = 0; i < 40; i++)
        for (int o = 16; o > 0; o >>= 1)
            acc[i] += __shfl_down_sync(0xffffffff, acc[i], o);
    int warp = threadIdx.x >> 5, lane = threadIdx.x & 31;
    if (lane == 0)
        for (int i = 0; i < 40; i++) red[warp * 40 + i] = acc[i];
    __syncthreads();
    if (threadIdx.x < 40) {
        float t = 0.f;
#pragma unroll
        for (int w = 0; w < 8; w++) t += red[w * 40 + threadIdx.x];
        atomicAdd(&g_stats[threadIdx.x], t);
    }
}

__global__ void finalize_kernel(const float* __restrict__ nf,
                                const float* __restrict__ bn_ws,
                                const float* __restrict__ bn_bs,
                                const float* __restrict__ bn_wv,
                                float* __restrict__ out)
{
    int t = blockIdx.x * blockDim.x + threadIdx.x;
    if (t >= N_NODES * 40) return;
    int c = t % 40;
    float val = g_tmp[t];
    const float invN = 1.f / (float)N_NODES;
    if (c < 16) {
        float m   = g_stats[c] * invN;
        float var = g_stats[16 + c] * invN - m * m;
        val = (val - m) * rsqrtf(var + BN_EPS) * bn_ws[c] + bn_bs[c];
    } else {
        int w = (c - 16) / 3;
        float vn = g_stats[32 + w] * (invN * (1.f / 3.f));
        val = val * rsqrtf(vn + BN_EPS) * bn_wv[w];
    }
    out[t] = val + nf[t];
}

/* ============================ launch ============================== */
extern "C" void kernel_launch(void* const* d_in, const int* in_sizes, int n_in,
                              void* d_out, int out_size)
{
    const float* nf    = (const float*)d_in[0];
    const float* esh   = (const float*)d_in[1];
    const float* ebas  = (const float*)d_in[2];
    const int*   eidx  = (const int*)  d_in[3];
    const float* W1    = (const float*)d_in[4];
    const float* b1    = (const float*)d_in[5];
    const float* W2    = (const float*)d_in[6];
    const float* b2    = (const float*)d_in[7];
    const float* W3    = (const float*)d_in[8];
    const float* b3    = (const float*)d_in[9];
    const float* si_w0 = (const float*)d_in[10];
    const float* si_w1 = (const float*)d_in[11];
    const float* bn_ws = (const float*)d_in[12];
    const float* bn_bs = (const float*)d_in[13];
    const float* bn_wv = (const float*)d_in[14];
    float* out = (float*)d_out;

    cudaFuncSetAttribute(edge_kernel, cudaFuncAttributeMaxDynamicSharedMemorySize, SM_TOTAL);

    /* launch order keeps edge_kernel at 0-indexed launch 3 (ncu slot) */
    prep_kernel<<<192, 256>>>(W2, W3);
    zero_agg_kernel<<<(N_NODES * 48 + 255) / 256, 256>>>();
    zero_stats_kernel<<<1, 64>>>();
    edge_kernel<<<(N_EDGES + 63) / 64, 256, SM_TOTAL>>>(nf, esh, ebas, eidx, W1, b1, b2, b3);
    node_kernel<<<(N_NODES + 255) / 256, 256>>>(si_w0, si_w1);
    stats_kernel<<<120, 256>>>();
    finalize_kernel<<<(N_NODES * 40 + 255) / 256, 256>>>(nf, bn_ws, bn_bs, bn_wv, out);
}

// round 16
// speedup vs baseline: 1.4344x; 1.0431x over previous
#include <cuda_runtime.h>
#include <cuda_fp16.h>

#define N_NODES 50000
#define N_EDGES 300000
#define SQRT3_INV 0.57735026918962576451f
#define ALPHA_C   0.20412414523193150818f   /* 1/sqrt(24) */
#define BN_EPS    1e-5f

typedef unsigned int u32;

/* ---------------- scratch (no allocation allowed) ---------------- */
__device__ float g_agg[N_NODES * 48];
__device__ float g_tmp[N_NODES * 40];
__device__ float g_stats[40];
__device__ __half g_w2t_h[64 * 64];      /* [n][k] transposed, fp16 */
__device__ __half g_w3t_h[768 * 64];     /* [w][k] transposed, fp16 */

__device__ __forceinline__ float silu_f(float x)    { return x / (1.f + __expf(-x)); }
__device__ __forceinline__ float sigmoid_f(float x) { return 1.f / (1.f + __expf(-x)); }

__device__ __forceinline__ u32 s2u(const void* p) {
    u32 a;
    asm("{ .reg .u64 t; cvta.to.shared.u64 t, %1; cvt.u32.u64 %0, t; }" : "=r"(a) : "l"(p));
    return a;
}
__device__ __forceinline__ void f16split(float x, u32& h, u32& l) {
    __half hb = __float2half(x);
    __half lb = __float2half(x - __half2float(hb));
    h = (u32)__half_as_ushort(hb);
    l = (u32)__half_as_ushort(lb);
}
/* extract fp16 (low/high per sh=0/16) from packed u32, to fp32 */
__device__ __forceinline__ float hsel(u32 v, u32 sh) {
    return __half2float(__ushort_as_half((unsigned short)(v >> sh)));
}

#define LDSM4(R, ADDR) \
    asm volatile("ldmatrix.sync.aligned.m8n8.x4.shared.b16 {%0,%1,%2,%3}, [%4];" \
        : "=r"((R)[0]), "=r"((R)[1]), "=r"((R)[2]), "=r"((R)[3]) : "r"(ADDR))

#define MMA_F16(C, A, B0, B1) \
    asm volatile("mma.sync.aligned.m16n8k16.row.col.f32.f16.f16.f32 " \
        "{%0,%1,%2,%3}, {%4,%5,%6,%7}, {%8,%9}, {%0,%1,%2,%3};" \
        : "+f"((C)[0]), "+f"((C)[1]), "+f"((C)[2]), "+f"((C)[3]) \
        : "r"((A)[0]), "r"((A)[1]), "r"((A)[2]), "r"((A)[3]), "r"(B0), "r"(B1))

/* named barriers: FULL[p] = 1+p, EMPTY[p] = 3+p */
#define BARS(id) asm volatile("bar.sync %0, 256;"   :: "r"(id) : "memory")
#define BARA(id) asm volatile("bar.arrive %0, 256;" :: "r"(id) : "memory")

/* ---------------- smem layout (bytes); rows padded to 72 halves --- */
constexpr int SM_A_HI = 0;         /* 64 x 144B */
constexpr int SM_A_LO = 9216;
constexpr int SM_B0   = 18432;     /* 64 x 144B, fp16 */
constexpr int SM_B1   = 27648;
constexpr int SM_P0   = 36864;     /* 64 x 144B, fp16 (72-half rows) */
constexpr int SM_P1   = 46080;
constexpr int SM_B2   = 55296;     /* 64 f   */
constexpr int SM_B3   = 55552;     /* 768 f  */
constexpr int SM_SH0  = 58624;     /* 64 f   */
constexpr int SM_SH1  = 58880;     /* 64x4 f */
constexpr int SM_SX   = 59904;     /* 64x17 f */
constexpr int SM_CB   = 64256;     /* 64x9 f */
constexpr int SM_VS   = 66560;     /* 64x25 f */
constexpr int SM_SRC  = 72960;     /* 64 int */
constexpr int SM_DST  = 73216;     /* 64 int */
constexpr int SM_TOTAL = 73472;    /* 71.75 KB -> 3 CTAs/SM */
/* prologue-only arrays aliased into P0 (dead until round-0 output) */
constexpr int SM_W1  = SM_P0;          /* 512 f  */
constexpr int SM_B1b = SM_P0 + 2048;   /* 64 f   */
constexpr int SM_BAS = SM_P0 + 2304;   /* 64x9 f */

/* ============ prep: transpose W2, W3 to fp16 ====================== */
__global__ void prep_kernel(const float* __restrict__ W2, const float* __restrict__ W3)
{
    int i = blockIdx.x * 256 + threadIdx.x;
    if (i < 64 * 64) {
        int n = i >> 6, k = i & 63;
        g_w2t_h[i] = __float2half(W2[k * 64 + n]);
    }
    if (i < 768 * 64) {
        int w = i >> 6, k = i & 63;
        g_w3t_h[i] = __float2half(W3[k * 768 + w]);
    }
}

/* split 16 fp32 -> fp16 hi/lo pairs, store one A row segment         */
__device__ __forceinline__ void split_store16(char* sm, int e, int j0, const float* xv)
{
    u32 hi[8], lo[8];
#pragma unroll
    for (int p = 0; p < 8; p++) {
        u32 h0, l0, h1, l1;
        f16split(xv[2 * p], h0, l0);
        f16split(xv[2 * p + 1], h1, l1);
        hi[p] = h0 | (h1 << 16);
        lo[p] = l0 | (l1 << 16);
    }
    u32 off = (u32)e * 144 + (u32)j0 * 2;
    *(uint4*)(sm + SM_A_HI + off)      = make_uint4(hi[0], hi[1], hi[2], hi[3]);
    *(uint4*)(sm + SM_A_HI + off + 16) = make_uint4(hi[4], hi[5], hi[6], hi[7]);
    *(uint4*)(sm + SM_A_LO + off)      = make_uint4(lo[0], lo[1], lo[2], lo[3]);
    *(uint4*)(sm + SM_A_LO + off + 16) = make_uint4(lo[4], lo[5], lo[6], lo[7]);
}

/* hi-only variant (H2 single-term A path)                            */
__device__ __forceinline__ void store16_hi(char* sm, int e, int j0, const float* xv)
{
    u32 hi[8];
#pragma unroll
    for (int p = 0; p < 8; p++) {
        u32 h0 = (u32)__half_as_ushort(__float2half(xv[2 * p]));
        u32 h1 = (u32)__half_as_ushort(__float2half(xv[2 * p + 1]));
        hi[p] = h0 | (h1 << 16);
    }
    u32 off = (u32)e * 144 + (u32)j0 * 2;
    *(uint4*)(sm + SM_A_HI + off)      = make_uint4(hi[0], hi[1], hi[2], hi[3]);
    *(uint4*)(sm + SM_A_HI + off + 16) = make_uint4(hi[4], hi[5], hi[6], hi[7]);
}

/* =================== edge kernel (warp-specialized) =============== */
__global__ void __launch_bounds__(256, 3)
edge_kernel(const float* __restrict__ nf,  const float* __restrict__ esh,
            const float* __restrict__ ebas, const int*  __restrict__ eidx,
            const float* __restrict__ W1,  const float* __restrict__ b1,
            const float* __restrict__ b2p, const float* __restrict__ b3p)
{
    extern __shared__ char sm[];
    const u32 sbv = s2u(sm);
    const int tid = threadIdx.x;
    const int wid = tid >> 5, lane = tid & 31;
    const int e = tid >> 2, q = tid & 3;
    const int ge = blockIdx.x * 64 + e;
    const bool active = ge < N_EDGES;
    int* sSrc = (int*)(sm + SM_SRC);
    int* sDst = (int*)(sm + SM_DST);

    /* ---- prologue (all 256 threads) ---- */
    if (tid < 128) ((float4*)(sm + SM_W1))[tid] = ((const float4*)W1)[tid];
    if (tid < 16)               ((float4*)(sm + SM_B1b))[tid]     = ((const float4*)b1)[tid];
    else if (tid < 32)          ((float4*)(sm + SM_B2))[tid - 16] = ((const float4*)b2p)[tid - 16];
    if (tid >= 32 && tid < 224) ((float4*)(sm + SM_B3))[tid - 32] = ((const float4*)b3p)[tid - 32];
#pragma unroll
    for (int s = 0; s < 2; s++) {                      /* B0 <- W2T, B1 <- W3 chunk 0 */
        int v = tid + s * 256;
        u32 doff = (u32)(v >> 3) * 144 + (u32)(v & 7) * 16;
        *(uint4*)(sm + SM_B0 + doff) = ((const uint4*)g_w2t_h)[v];
        *(uint4*)(sm + SM_B1 + doff) = ((const uint4*)g_w3t_h)[v];
    }
    if (q == 0) {
        float4 sh = active ? *(const float4*)(esh + (size_t)ge * 4) : make_float4(0, 0, 0, 0);
        ((float*)(sm + SM_SH0))[e] = sh.x;
        ((float*)(sm + SM_SH1))[e * 4 + 0] = sh.y;
        ((float*)(sm + SM_SH1))[e * 4 + 1] = sh.z;
        ((float*)(sm + SM_SH1))[e * 4 + 2] = sh.w;
        sSrc[e] = active ? eidx[ge] : 0;
        sDst[e] = active ? eidx[N_EDGES + ge] : 0;
    } else if (q == 1) {
        float4 bA = active ? *(const float4*)(ebas + (size_t)ge * 8)     : make_float4(0, 0, 0, 0);
        float4 bB = active ? *(const float4*)(ebas + (size_t)ge * 8 + 4) : make_float4(0, 0, 0, 0);
        float* bs = (float*)(sm + SM_BAS) + e * 9;
        bs[0] = bA.x; bs[1] = bA.y; bs[2] = bA.z; bs[3] = bA.w;
        bs[4] = bB.x; bs[5] = bB.y; bs[6] = bB.z; bs[7] = bB.w;
    }
    __syncthreads();

    {   /* gather node features + coefficients */
        const int src = sSrc[e];
        const float* nfr = nf + (size_t)src * 40;
        const float sh0 = ((float*)(sm + SM_SH0))[e];
        const float s1x = ((float*)(sm + SM_SH1))[e * 4 + 0];
        const float s1y = ((float*)(sm + SM_SH1))[e * 4 + 1];
        const float s1z = ((float*)(sm + SM_SH1))[e * 4 + 2];
        for (int u = q; u < 16; u += 4)
            ((float*)(sm + SM_SX))[e * 17 + u] = active ? nfr[u] : 0.f;
        for (int u = q; u < 8; u += 4) {
            float v0 = active ? nfr[16 + u * 3 + 0] : 0.f;
            float v1 = active ? nfr[16 + u * 3 + 1] : 0.f;
            float v2 = active ? nfr[16 + u * 3 + 2] : 0.f;
            float* vs = (float*)(sm + SM_VS);
            vs[e * 25 + u * 3 + 0] = v0 * sh0;
            vs[e * 25 + u * 3 + 1] = v1 * sh0;
            vs[e * 25 + u * 3 + 2] = v2 * sh0;
            ((float*)(sm + SM_CB))[e * 9 + u] = (v0 * s1x + v1 * s1y + v2 * s1z) * SQRT3_INV;
        }
    }

    {   /* H1 = silu(basis @ W1 + b1) -> A hi/lo (round 0 is 2-term) */
        const float* w1s = (const float*)(sm + SM_W1);
        const float* b1s = (const float*)(sm + SM_B1b);
        const float* bs  = (const float*)(sm + SM_BAS) + e * 9;
        float bk[8];
#pragma unroll
        for (int k = 0; k < 8; k++) bk[k] = bs[k];
        const int j0 = q * 16;
        float xv[16];
#pragma unroll
        for (int jj = 0; jj < 16; jj++) {
            float x = b1s[j0 + jj];
#pragma unroll
            for (int k = 0; k < 8; k++) x += bk[k] * w1s[k * 64 + j0 + jj];
            xv[jj] = silu_f(x);
        }
        split_store16(sm, e, j0, xv);
    }
    __syncthreads();

    if (wid < 4) {
        /* ========== PRODUCER: 2x2 tiling, persistent A, N-streamed = */
        const int mi = wid & 1, ni = wid >> 1;
        const int m0 = mi * 32, n0 = ni * 32;
        const u32 arow = (u32)(m0 + ((lane >> 3) & 1) * 8 + (lane & 7)) * 144
                       + (u32)((lane >> 4) & 1) * 16;
        const u32 boffr = (u32)(((lane >> 4) & 1) * 8 + (lane & 7)) * 144
                        + (u32)((lane >> 3) & 1) * 16;
        const int cg = lane >> 2, c2 = (lane & 3) * 2;

        u32 ah[2][4][4];
#pragma unroll
        for (int mt = 0; mt < 2; mt++)
#pragma unroll
            for (int ks = 0; ks < 4; ks++)
                LDSM4(ah[mt][ks], sbv + SM_A_HI + arow + mt * 2304 + ks * 32);

        /* ---- round 0: P = H1 @ W2^T, 2-term; hi->P0, lo->P1 ---- */
        {
            const float* bias = (const float*)(sm + SM_B2);
#pragma unroll
            for (int ntp = 0; ntp < 2; ntp++) {
                float acc[2][2][4];
#pragma unroll
                for (int mt = 0; mt < 2; mt++)
#pragma unroll
                    for (int n2 = 0; n2 < 2; n2++)
#pragma unroll
                        for (int i = 0; i < 4; i++) acc[mt][n2][i] = 0.f;
#pragma unroll
                for (int ks = 0; ks < 4; ks++) {
                    u32 bh[4], al0[4], al1[4];
                    LDSM4(bh, sbv + SM_B0 + boffr + (u32)(n0 + ntp * 16) * 144 + ks * 32);
                    LDSM4(al0, sbv + SM_A_LO + arow + ks * 32);
                    LDSM4(al1, sbv + SM_A_LO + arow + 2304 + ks * 32);
#pragma unroll
                    for (int n2 = 0; n2 < 2; n2++) {
                        MMA_F16(acc[0][n2], ah[0][ks], bh[n2 * 2], bh[n2 * 2 + 1]);
                        MMA_F16(acc[0][n2], al0,       bh[n2 * 2], bh[n2 * 2 + 1]);
                        MMA_F16(acc[1][n2], ah[1][ks], bh[n2 * 2], bh[n2 * 2 + 1]);
                        MMA_F16(acc[1][n2], al1,       bh[n2 * 2], bh[n2 * 2 + 1]);
                    }
                }
#pragma unroll
                for (int n2 = 0; n2 < 2; n2++) {
                    const int col = n0 + ntp * 16 + n2 * 8 + c2;
                    float2 bv = *(const float2*)&bias[col];
#pragma unroll
                    for (int mt = 0; mt < 2; mt++) {
                        const int row0 = m0 + mt * 16 + cg;
                        float v0 = acc[mt][n2][0] + bv.x, v1 = acc[mt][n2][1] + bv.y;
                        float v2 = acc[mt][n2][2] + bv.x, v3 = acc[mt][n2][3] + bv.y;
                        __half2 h01 = __floats2half2_rn(v0, v1);
                        __half2 h23 = __floats2half2_rn(v2, v3);
                        *(__half2*)(sm + SM_P0 + row0 * 144 + col * 2)       = h01;
                        *(__half2*)(sm + SM_P0 + (row0 + 8) * 144 + col * 2) = h23;
                        __half2 l01 = __floats2half2_rn(v0 - __low2float(h01), v1 - __high2float(h01));
                        __half2 l23 = __floats2half2_rn(v2 - __low2float(h23), v3 - __high2float(h23));
                        *(__half2*)(sm + SM_P1 + row0 * 144 + col * 2)       = l01;
                        *(__half2*)(sm + SM_P1 + (row0 + 8) * 144 + col * 2) = l23;
                    }
                }
            }
            BARA(1);                                 /* FULL0 */
            BARS(3);                                 /* EMPTY0: H2 in A smem */
#pragma unroll
            for (int mt = 0; mt < 2; mt++)
#pragma unroll
                for (int ks = 0; ks < 4; ks++)
                    LDSM4(ah[mt][ks], sbv + SM_A_HI + arow + mt * 2304 + ks * 32);
        }

        /* ---- rounds 1..12: single-term A (persistent regs) ---- */
#pragma unroll 1
        for (int r = 1; r <= 12; r++) {
            const int p = r & 1;
            if (r >= 3) BARS(3 + p);                 /* EMPTY[p] */
            const u32 baseB = sbv + (p ? SM_B1 : SM_B0);
            char* PB = sm + (p ? SM_P1 : SM_P0);
            const float* bias = (const float*)(sm + SM_B3) + (r - 1) * 64;
#pragma unroll
            for (int ntp = 0; ntp < 2; ntp++) {
                float acc[2][2][4];
#pragma unroll
                for (int mt = 0; mt < 2; mt++)
#pragma unroll
                    for (int n2 = 0; n2 < 2; n2++)
#pragma unroll
                        for (int i = 0; i < 4; i++) acc[mt][n2][i] = 0.f;
#pragma unroll
                for (int ks = 0; ks < 4; ks++) {
                    u32 bh[4];
                    LDSM4(bh, baseB + boffr + (u32)(n0 + ntp * 16) * 144 + ks * 32);
#pragma unroll
                    for (int n2 = 0; n2 < 2; n2++) {
                        MMA_F16(acc[0][n2], ah[0][ks], bh[n2 * 2], bh[n2 * 2 + 1]);
                        MMA_F16(acc[1][n2], ah[1][ks], bh[n2 * 2], bh[n2 * 2 + 1]);
                    }
                }
#pragma unroll
                for (int n2 = 0; n2 < 2; n2++) {
                    const int col = n0 + ntp * 16 + n2 * 8 + c2;
                    float2 bv = *(const float2*)&bias[col];
#pragma unroll
                    for (int mt = 0; mt < 2; mt++) {
                        const int row0 = m0 + mt * 16 + cg;
                        __half2 h01 = __floats2half2_rn(acc[mt][n2][0] + bv.x, acc[mt][n2][1] + bv.y);
                        __half2 h23 = __floats2half2_rn(acc[mt][n2][2] + bv.x, acc[mt][n2][3] + bv.y);
                        *(__half2*)(PB + row0 * 144 + col * 2)       = h01;
                        *(__half2*)(PB + (row0 + 8) * 144 + col * 2) = h23;
                    }
                }
            }
            BARA(1 + p);                             /* FULL[p] */
        }
    } else {
        /* =============== CONSUMER: warps 4-7 ======================= */
        const int tp = tid - 128;
        const int ce = tp >> 1, cq = tp & 1;
        const bool cact = (blockIdx.x * 64 + ce) < N_EDGES;
        const int eP = ce * 144;                     /* byte row offset in P */
        const u32 shx = (u32)cq * 16;                /* half-select shift */
        const float sh0e = ((const float*)(sm + SM_SH0))[ce];
        const float* sxs = (const float*)(sm + SM_SX) + ce * 17;
        const float* cbs = (const float*)(sm + SM_CB) + ce * 9;
        const float* vse = (const float*)(sm + SM_VS) + ce * 25;

        float rs[12], rtsv[4], rv[4][3];
#pragma unroll
        for (int k = 0; k < 12; k++) rs[k] = 0.f;
#pragma unroll
        for (int t = 0; t < 4; t++) {
            rtsv[t] = 0.f;
            rv[t][0] = 0.f; rv[t][1] = 0.f; rv[t][2] = 0.f;
        }

#pragma unroll
        for (int r = 0; r <= 12; r++) {
            BARS(1 + (r & 1));                       /* FULL[p] */
            if (r <= 10) {                           /* stage W3 chunk r+1 */
                char* dB = sm + ((r & 1) ? SM_B1 : SM_B0);
                const uint4* srcB = ((const uint4*)g_w3t_h) + (r + 1) * 512;
#pragma unroll
                for (int s = 0; s < 4; s++) {
                    int v = tp + s * 128;
                    u32 doff = (u32)(v >> 3) * 144 + (u32)(v & 7) * 16;
                    *(uint4*)(dB + doff) = srcB[v];
                }
            }
            if (r == 0) {
                /* H2 = silu(hi+lo) -> A hi only (single-term W3 rounds) */
                const int j0 = cq * 32;
                float xv[16];
#pragma unroll
                for (int half = 0; half < 2; half++) {
#pragma unroll
                    for (int jj = 0; jj < 16; jj += 2) {
                        const int c = j0 + half * 16 + jj;
                        float2 hf = __half22float2(*(const __half2*)(sm + SM_P0 + eP + c * 2));
                        float2 lf = __half22float2(*(const __half2*)(sm + SM_P1 + eP + c * 2));
                        xv[jj]     = silu_f(hf.x + lf.x);
                        xv[jj + 1] = silu_f(hf.y + lf.y);
                    }
                    store16_hi(sm, ce, j0 + half * 16, xv);
                }
                BARA(3);                             /* EMPTY0: after H2 + P1-lo read */
            } else {
                const char* PB = sm + ((r & 1) ? SM_P1 : SM_P0);
                /* vector-load whole P row into regs */
                u32 row[32];
#pragma unroll
                for (int i = 0; i < 8; i++) {
                    uint4 v4 = *(const uint4*)(PB + eP + i * 16);
                    row[i * 4 + 0] = v4.x; row[i * 4 + 1] = v4.y;
                    row[i * 4 + 2] = v4.z; row[i * 4 + 3] = v4.w;
                }
                /* early release: P row is in regs, B staging done */
                if (r <= 10) BARA(3 + (r & 1));      /* EMPTY[p] */
                const int cc = r - 1;
                if (cc < 9) {                        /* SS (cc<6) or VV */
                    const bool isSS = (cc < 6);
                    const int base = cc * 64;
                    const int sub = isSS ? 0 : 384;
                    const int bm2 = (base % 24) / 2;     /* 0,8,4,... */
                    const int d = (base - sub) / 24;
                    const float* coef = isSS ? sxs : cbs;
#pragma unroll
                    for (int k = 0; k < 12; k++) {
                        const int m = (k - bm2 + 12) % 12;   /* compile-time */
                        const int u0 = d + ((k < bm2) ? 1 : 0);
                        float a = hsel(row[m], shx) * coef[u0]
                                + hsel(row[m + 12], shx) * coef[u0 + 1];
                        if (m < 8)
                            a += hsel(row[m + 24], shx) * coef[u0 + 2];
                        rs[k] += isSS ? a * sh0e : a;
                    }
                } else if (cc < 11) {                /* SV */
                    const int uoff = (cc == 9) ? 0 : 8;
#pragma unroll
                    for (int t = 0; t < 4; t++) {
                        float a = 0.f;
#pragma unroll
                        for (int u = 0; u < 8; u++)
                            a += hsel(row[u * 4 + t], shx) * sxs[uoff + u];
                        rtsv[t] += a;
                    }
                } else {                             /* VS */
#pragma unroll
                    for (int t = 0; t < 4; t++) {
                        float pv[8];
#pragma unroll
                        for (int u = 0; u < 8; u++)
                            pv[u] = hsel(row[u * 4 + t], shx);
#pragma unroll
                        for (int i = 0; i < 3; i++) {
                            float a = 0.f;
#pragma unroll
                            for (int u = 0; u < 8; u++) a += pv[u] * vse[u * 3 + i];
                            rv[t][i] += a;
                        }
                    }
                }
            }
        }

        /* ---- finalize + scatter ---- */
        if (cact) {
            const int dst = sDst[ce];
            const float* sh1 = (const float*)(sm + SM_SH1) + ce * 4;
            float* ap = &g_agg[(size_t)dst * 48];
#pragma unroll
            for (int k = 0; k < 12; k++)
                atomicAdd(ap + cq + 2 * k, rs[k] * ALPHA_C);
#pragma unroll
            for (int t = 0; t < 4; t++) {
                const int w = cq + 2 * t;
#pragma unroll
                for (int i = 0; i < 3; i++)
                    atomicAdd(ap + 24 + w * 3 + i, (rv[t][i] + rtsv[t] * sh1[i]) * ALPHA_C);
            }
        }
    }
}

/* =================== node post-processing ========================= */
__global__ void zero_agg_kernel()
{
    int i = blockIdx.x * blockDim.x + threadIdx.x;
    if (i < N_NODES * 48) g_agg[i] = 0.f;
}
__global__ void zero_stats_kernel()
{
    if (threadIdx.x < 40) g_stats[threadIdx.x] = 0.f;
}

__global__ void node_kernel(const float* __restrict__ si_w0, const float* __restrict__ si_w1)
{
    __shared__ float w0[256], w1[64];
    int tid = threadIdx.x;
    if (tid < 256) w0[tid] = si_w0[tid] * 0.25f;
    if (tid < 64)  w1[tid] = si_w1[tid] * 0.35355339059327373f;
    __syncthreads();
    int n = blockIdx.x * blockDim.x + tid;
    if (n >= N_NODES) return;
    const float* a = &g_agg[(size_t)n * 48];
    float s[16], v[24];
#pragma unroll
    for (int u = 0; u < 16; u++) s[u] = silu_f(a[u]);
#pragma unroll
    for (int u = 0; u < 8; u++) {
        float g = sigmoid_f(a[16 + u]);
        v[u * 3 + 0] = a[24 + u * 3 + 0] * g;
        v[u * 3 + 1] = a[24 + u * 3 + 1] * g;
        v[u * 3 + 2] = a[24 + u * 3 + 2] * g;
    }
    float out[40];
#pragma unroll
    for (int w = 0; w < 16; w++) {
        float acc = 0.f;
#pragma unroll
        for (int u = 0; u < 16; u++) acc += s[u] * w0[u * 16 + w];
        out[w] = acc;
    }
#pragma unroll
    for (int w = 0; w < 8; w++) {
#pragma unroll
        for (int i = 0; i < 3; i++) {
            float acc = 0.f;
#pragma unroll
            for (int u = 0; u < 8; u++) acc += v[u * 3 + i] * w1[u * 8 + w];
            out[16 + w * 3 + i] = acc;
        }
    }
#pragma unroll
    for (int i = 0; i < 40; i += 4)
        *(float4*)&g_tmp[(size_t)n * 40 + i] = make_float4(out[i], out[i + 1], out[i + 2], out[i + 3]);
}

__global__ void stats_kernel()
{
    __shared__ float red[8 * 40];
    float acc[40];
#pragma unroll
    for (int i = 0; i < 40; i++) acc[i] = 0.f;
    for (int n = blockIdx.x * blockDim.x + threadIdx.x; n < N_NODES;
         n += gridDim.x * blockDim.x) {
        const float* t = &g_tmp[(size_t)n * 40];
#pragma unroll
        for (int c = 0; c < 16; c++) { float x = t[c]; acc[c] += x; acc[16 + c] += x * x; }
#pragma unroll
        for (int w = 0; w < 8; w++) {
            float x0 = t[16 + w * 3], x1 = t[17 + w * 3], x2 = t[18 + w * 3];
            acc[32 + w] += x0 * x0 + x1 * x1 + x2 * x2;
        }
    }
#pragma unroll
    for (int i = 0; i < 40; i++)
        for (int o = 16; o > 0; o >>= 1)
            acc[i] += __shfl_down_sync(0xffffffff, acc[i], o);
    int warp = threadIdx.x >> 5, lane = threadIdx.x & 31;
    if (lane == 0)
        for (int i = 0; i < 40; i++) red[warp * 40 + i] = acc[i];
    __syncthreads();
    if (threadIdx.x < 40) {
        float t = 0.f;
#pragma unroll
        for (int w = 0; w < 8; w++) t += red[w * 40 + threadIdx.x];
        atomicAdd(&g_stats[threadIdx.x], t);
    }
}

__global__ void finalize_kernel(const float* __restrict__ nf,
                                const float* __restrict__ bn_ws,
                                const float* __restrict__ bn_bs,
                                const float* __restrict__ bn_wv,
                                float* __restrict__ out)
{
    int t = blockIdx.x * blockDim.x + threadIdx.x;
    if (t >= N_NODES * 40) return;
    int c = t % 40;
    float val = g_tmp[t];
    const float invN = 1.f / (float)N_NODES;
    if (c < 16) {
        float m   = g_stats[c] * invN;
        float var = g_stats[16 + c] * invN - m * m;
        val = (val - m) * rsqrtf(var + BN_EPS) * bn_ws[c] + bn_bs[c];
    } else {
        int w = (c - 16) / 3;
        float vn = g_stats[32 + w] * (invN * (1.f / 3.f));
        val = val * rsqrtf(vn + BN_EPS) * bn_wv[w];
    }
    out[t] = val + nf[t];
}

/* ============================ launch ============================== */
extern "C" void kernel_launch(void* const* d_in, const int* in_sizes, int n_in,
                              void* d_out, int out_size)
{
    const float* nf    = (const float*)d_in[0];
    const float* esh   = (const float*)d_in[1];
    const float* ebas  = (const float*)d_in[2];
    const int*   eidx  = (const int*)  d_in[3];
    const float* W1    = (const float*)d_in[4];
    const float* b1    = (const float*)d_in[5];
    const float* W2    = (const float*)d_in[6];
    const float* b2    = (const float*)d_in[7];
    const float* W3    = (const float*)d_in[8];
    const float* b3    = (const float*)d_in[9];
    const float* si_w0 = (const float*)d_in[10];
    const float* si_w1 = (const float*)d_in[11];
    const float* bn_ws = (const float*)d_in[12];
    const float* bn_bs = (const float*)d_in[13];
    const float* bn_wv = (const float*)d_in[14];
    float* out = (float*)d_out;

    cudaFuncSetAttribute(edge_kernel, cudaFuncAttributeMaxDynamicSharedMemorySize, SM_TOTAL);

    /* launch order keeps edge_kernel at 0-indexed launch 3 (ncu slot) */
    prep_kernel<<<192, 256>>>(W2, W3);
    zero_agg_kernel<<<(N_NODES * 48 + 255) / 256, 256>>>();
    zero_stats_kernel<<<1, 64>>>();
    edge_kernel<<<(N_EDGES + 63) / 64, 256, SM_TOTAL>>>(nf, esh, ebas, eidx, W1, b1, b2, b3);
    node_kernel<<<(N_NODES + 255) / 256, 256>>>(si_w0, si_w1);
    stats_kernel<<<120, 256>>>();
    finalize_kernel<<<(N_NODES * 40 + 255) / 256, 256>>>(nf, bn_ws, bn_bs, bn_wv, out);
}